// round 1
// baseline (speedup 1.0000x reference)
#include <cuda_runtime.h>

typedef unsigned long long ull;

#define NNODES 50000
#define NEDGES 1600000
#define NGRAPH 4
#define HID    64
#define NLAYERS 5

// ---------------- device scratch (no allocations allowed) ----------------
__device__ float g_h[NNODES * HID];
__device__ float g_agg[NNODES * HID];
__device__ float g_pooled[NGRAPH * HID];
__device__ int   g_cnt[NGRAPH];

// ---------------- helpers ----------------
__device__ __forceinline__ float silu_f(float x) {
    // sigmoid(x) = 0.5*tanh(0.5x)+0.5  -> one MUFU instead of EX2+RCP
    float t;
    asm("tanh.approx.f32 %0, %1;" : "=f"(t) : "f"(x * 0.5f));
    return x * 0.5f * t + x * 0.5f;
}
__device__ __forceinline__ ull fma2(ull a, ull b, ull c) {
    ull d;
    asm("fma.rn.f32x2 %0, %1, %2, %3;" : "=l"(d) : "l"(a), "l"(b), "l"(c));
    return d;
}
__device__ __forceinline__ ull pack2(float lo, float hi) {
    ull r;
    asm("mov.b64 %0, {%1, %2};" : "=l"(r) : "f"(lo), "f"(hi));
    return r;
}
__device__ __forceinline__ ull dup2(float x) {
    ull r;
    asm("mov.b64 %0, {%1, %1};" : "=l"(r) : "f"(x));
    return r;
}
__device__ __forceinline__ void unpack2(ull v, float& lo, float& hi) {
    asm("mov.b64 {%0, %1}, %2;" : "=f"(lo), "=f"(hi) : "l"(v));
}
__device__ __forceinline__ void red_add4(float* p, float a, float b, float c, float d) {
    asm volatile("red.global.add.v4.f32 [%0], {%1, %2, %3, %4};"
                 :: "l"(p), "f"(a), "f"(b), "f"(c), "f"(d) : "memory");
}

// one k-step of GEMM1: acc[0..31] (pairs) += in * W[k][:]
__device__ __forceinline__ void kstep(ull in2, const float* __restrict__ wrow, ull* acc) {
    const ulonglong2* w = reinterpret_cast<const ulonglong2*>(wrow);
#pragma unroll
    for (int q = 0; q < 16; ++q) {
        ulonglong2 t = w[q];
        acc[2 * q]     = fma2(in2, t.x, acc[2 * q]);
        acc[2 * q + 1] = fma2(in2, t.y, acc[2 * q + 1]);
    }
}

// ---------------- zero kernels (graph replays must re-init scratch) ----------------
__global__ void zero_agg_kernel() {
    int i = blockIdx.x * blockDim.x + threadIdx.x;
    for (; i < NNODES * HID; i += gridDim.x * blockDim.x) g_agg[i] = 0.f;
}
__global__ void zero_pool_kernel() {
    int t = threadIdx.x;
    if (t < NGRAPH * HID) g_pooled[t] = 0.f;
    if (t < NGRAPH) g_cnt[t] = 0;
}

// ---------------- encoder ----------------
__global__ void __launch_bounds__(128) encoder_kernel(
    const float* __restrict__ x, const int* __restrict__ batch,
    const float* __restrict__ caseP, const float* __restrict__ bcP,
    const float* __restrict__ W1, const float* __restrict__ b1,
    const float* __restrict__ W2, const float* __restrict__ b2,
    const float* __restrict__ gam, const float* __restrict__ bet)
{
    __shared__ float sW1[16 * 64];
    __shared__ float sW2[64 * 64];
    __shared__ float sb1[64], sb2[64], sg[64], sbe[64];
    __shared__ float sy[4][64];
    int tid = threadIdx.x;
    for (int i = tid; i < 16 * 64; i += 128) sW1[i] = W1[i];
    for (int i = tid; i < 64 * 64; i += 128) sW2[i] = W2[i];
    if (tid < 64) { sb1[tid] = b1[tid]; sb2[tid] = b2[tid]; sg[tid] = gam[tid]; sbe[tid] = bet[tid]; }
    __syncthreads();

    int lane = tid & 31, warp = tid >> 5;
    int j0 = lane, j1 = lane + 32;
    for (int n = blockIdx.x * 4 + warp; n < NNODES; n += gridDim.x * 4) {
        float in[16];
        const float* xr = x + n * 8;
#pragma unroll
        for (int k = 0; k < 8; ++k) in[k] = xr[k];
        int b = batch[n];
#pragma unroll
        for (int k = 0; k < 4; ++k) in[8 + k]  = caseP[b * 4 + k];
#pragma unroll
        for (int k = 0; k < 4; ++k) in[12 + k] = bcP[b * 4 + k];

        float a0 = sb1[j0], a1 = sb1[j1];
#pragma unroll
        for (int k = 0; k < 16; ++k) {
            a0 = fmaf(in[k], sW1[k * 64 + j0], a0);
            a1 = fmaf(in[k], sW1[k * 64 + j1], a1);
        }
        a0 = silu_f(a0); a1 = silu_f(a1);
        sy[warp][j0] = a0; sy[warp][j1] = a1;
        __syncwarp();
        float z0 = sb2[j0], z1 = sb2[j1];
#pragma unroll 4
        for (int k = 0; k < 64; ++k) {
            float v = sy[warp][k];
            z0 = fmaf(v, sW2[k * 64 + j0], z0);
            z1 = fmaf(v, sW2[k * 64 + j1], z1);
        }
        float s = z0 + z1, ss = z0 * z0 + z1 * z1;
#pragma unroll
        for (int o = 16; o > 0; o >>= 1) {
            s  += __shfl_xor_sync(0xffffffffu, s, o);
            ss += __shfl_xor_sync(0xffffffffu, ss, o);
        }
        float m = s * (1.f / 64.f);
        float rs = rsqrtf(ss * (1.f / 64.f) - m * m + 1e-5f);
        g_h[n * HID + j0] = (z0 - m) * rs * sg[j0] + sbe[j0];
        g_h[n * HID + j1] = (z1 - m) * rs * sg[j1] + sbe[j1];
        __syncwarp();
    }
}

// ---------------- edge MLP + scatter (dominant kernel) ----------------
// lane = edge; 32 edges per warp-tile; f32x2 packed accumulators (64 outputs = 32 b64)
__global__ void __launch_bounds__(128, 3) edge_kernel(
    const int* __restrict__ ei, const float* __restrict__ ea,
    const float* __restrict__ W1, const float* __restrict__ b1,
    const float* __restrict__ W2, const float* __restrict__ b2,
    const float* __restrict__ gam, const float* __restrict__ bet)
{
    extern __shared__ float smem[];
    float* sW1 = smem;                 // 133*64
    float* sW2 = sW1 + 133 * 64;       // 64*64
    float* sb1 = sW2 + 64 * 64;
    float* sb2 = sb1 + 64;
    float* sg  = sb2 + 64;
    float* sbe = sg + 64;
    int tid = threadIdx.x;
    for (int i = tid; i < 133 * 64; i += 128) sW1[i] = W1[i];
    for (int i = tid; i < 64 * 64; i += 128) sW2[i] = W2[i];
    if (tid < 64) { sb1[tid] = b1[tid]; sb2[tid] = b2[tid]; sg[tid] = gam[tid]; sbe[tid] = bet[tid]; }
    __syncthreads();

    const int lane = tid & 31;
    const int warp = tid >> 5;
    const int ntiles = NEDGES / 32;  // 1.6M % 32 == 0
    for (int t = blockIdx.x * 4 + warp; t < ntiles; t += gridDim.x * 4) {
        const int e   = t * 32 + lane;
        const int src = ei[e];            // x_j
        const int dst = ei[NEDGES + e];   // x_i (aggregation target)
        const float4* __restrict__ Hd = reinterpret_cast<const float4*>(g_h + dst * HID);
        const float4* __restrict__ Hs = reinterpret_cast<const float4*>(g_h + src * HID);
        const float*  __restrict__ er = ea + e * 5;

        ull acc[32];
        {
            const float2* bb = reinterpret_cast<const float2*>(sb1);
#pragma unroll
            for (int p = 0; p < 32; ++p) { float2 v = bb[p]; acc[p] = pack2(v.x, v.y); }
        }
        // k = 0..63 : h[dst]
#pragma unroll 2
        for (int c = 0; c < 16; ++c) {
            float4 v = Hd[c];
            const float* w = sW1 + (4 * c) * HID;
            kstep(dup2(v.x), w,            acc);
            kstep(dup2(v.y), w + HID,      acc);
            kstep(dup2(v.z), w + 2 * HID,  acc);
            kstep(dup2(v.w), w + 3 * HID,  acc);
        }
        // k = 64..127 : h[src]
#pragma unroll 2
        for (int c = 0; c < 16; ++c) {
            float4 v = Hs[c];
            const float* w = sW1 + (64 + 4 * c) * HID;
            kstep(dup2(v.x), w,            acc);
            kstep(dup2(v.y), w + HID,      acc);
            kstep(dup2(v.z), w + 2 * HID,  acc);
            kstep(dup2(v.w), w + 3 * HID,  acc);
        }
        // k = 128..132 : edge_attr
        {
            float e0 = er[0], e1 = er[1], e2 = er[2], e3 = er[3], e4 = er[4];
            kstep(dup2(e0), sW1 + 128 * HID, acc);
            kstep(dup2(e1), sW1 + 129 * HID, acc);
            kstep(dup2(e2), sW1 + 130 * HID, acc);
            kstep(dup2(e3), sW1 + 131 * HID, acc);
            kstep(dup2(e4), sW1 + 132 * HID, acc);
        }

        // silu + GEMM2
        ull acc2[32];
        {
            const float2* bb = reinterpret_cast<const float2*>(sb2);
#pragma unroll
            for (int p = 0; p < 32; ++p) { float2 v = bb[p]; acc2[p] = pack2(v.x, v.y); }
        }
#pragma unroll 2
        for (int p = 0; p < 32; ++p) {
            float x0, x1;
            unpack2(acc[p], x0, x1);
            ull i0 = dup2(silu_f(x0));
            ull i1 = dup2(silu_f(x1));
            const ulonglong2* w0 = reinterpret_cast<const ulonglong2*>(sW2 + (2 * p) * HID);
            const ulonglong2* w1 = reinterpret_cast<const ulonglong2*>(sW2 + (2 * p + 1) * HID);
#pragma unroll
            for (int q = 0; q < 16; ++q) {
                ulonglong2 wa = w0[q];
                ulonglong2 wb = w1[q];
                acc2[2 * q]     = fma2(i0, wa.x, acc2[2 * q]);
                acc2[2 * q + 1] = fma2(i0, wa.y, acc2[2 * q + 1]);
                acc2[2 * q]     = fma2(i1, wb.x, acc2[2 * q]);
                acc2[2 * q + 1] = fma2(i1, wb.y, acc2[2 * q + 1]);
            }
        }

        // LayerNorm over the 64 outputs (all in registers) + vector scatter-add
        float y[64];
        float s = 0.f, ss = 0.f;
#pragma unroll
        for (int p = 0; p < 32; ++p) {
            float a, b;
            unpack2(acc2[p], a, b);
            y[2 * p] = a; y[2 * p + 1] = b;
            s += a + b; ss += a * a + b * b;
        }
        float m  = s * (1.f / 64.f);
        float rs = rsqrtf(ss * (1.f / 64.f) - m * m + 1e-5f);
        float* ag = g_agg + dst * HID;
#pragma unroll
        for (int q = 0; q < 16; ++q) {
            float o0 = (y[4 * q + 0] - m) * rs * sg[4 * q + 0] + sbe[4 * q + 0];
            float o1 = (y[4 * q + 1] - m) * rs * sg[4 * q + 1] + sbe[4 * q + 1];
            float o2 = (y[4 * q + 2] - m) * rs * sg[4 * q + 2] + sbe[4 * q + 2];
            float o3 = (y[4 * q + 3] - m) * rs * sg[4 * q + 3] + sbe[4 * q + 3];
            red_add4(ag + 4 * q, o0, o1, o2, o3);
        }
    }
}

// ---------------- node MLP (residual update) ----------------
__global__ void __launch_bounds__(128) node_kernel(
    const float* __restrict__ W1, const float* __restrict__ b1,
    const float* __restrict__ W2, const float* __restrict__ b2,
    const float* __restrict__ gam, const float* __restrict__ bet)
{
    extern __shared__ float smem[];
    float* sW1 = smem;                 // 128*64
    float* sW2 = sW1 + 128 * 64;       // 64*64
    float* sb1 = sW2 + 64 * 64;
    float* sb2 = sb1 + 64;
    float* sg  = sb2 + 64;
    float* sbe = sg + 64;
    float* sy  = sbe + 64;             // 4 warps * 64
    int tid = threadIdx.x;
    for (int i = tid; i < 128 * 64; i += 128) sW1[i] = W1[i];
    for (int i = tid; i < 64 * 64; i += 128) sW2[i] = W2[i];
    if (tid < 64) { sb1[tid] = b1[tid]; sb2[tid] = b2[tid]; sg[tid] = gam[tid]; sbe[tid] = bet[tid]; }
    __syncthreads();

    int lane = tid & 31, warp = tid >> 5;
    float* syw = sy + warp * 64;
    int j0 = lane, j1 = lane + 32;
    for (int n = blockIdx.x * 4 + warp; n < NNODES; n += gridDim.x * 4) {
        const float4* Hr = reinterpret_cast<const float4*>(g_h + n * HID);
        const float4* Ar = reinterpret_cast<const float4*>(g_agg + n * HID);
        float a0 = sb1[j0], a1 = sb1[j1];
#pragma unroll 4
        for (int c = 0; c < 16; ++c) {
            float4 v = Hr[c];
            const float* w = sW1 + 4 * c * 64;
            a0 = fmaf(v.x, w[j0], a0);           a1 = fmaf(v.x, w[j1], a1);
            a0 = fmaf(v.y, w[64 + j0], a0);      a1 = fmaf(v.y, w[64 + j1], a1);
            a0 = fmaf(v.z, w[128 + j0], a0);     a1 = fmaf(v.z, w[128 + j1], a1);
            a0 = fmaf(v.w, w[192 + j0], a0);     a1 = fmaf(v.w, w[192 + j1], a1);
        }
#pragma unroll 4
        for (int c = 0; c < 16; ++c) {
            float4 v = Ar[c];
            const float* w = sW1 + (64 + 4 * c) * 64;
            a0 = fmaf(v.x, w[j0], a0);           a1 = fmaf(v.x, w[j1], a1);
            a0 = fmaf(v.y, w[64 + j0], a0);      a1 = fmaf(v.y, w[64 + j1], a1);
            a0 = fmaf(v.z, w[128 + j0], a0);     a1 = fmaf(v.z, w[128 + j1], a1);
            a0 = fmaf(v.w, w[192 + j0], a0);     a1 = fmaf(v.w, w[192 + j1], a1);
        }
        a0 = silu_f(a0); a1 = silu_f(a1);
        syw[j0] = a0; syw[j1] = a1;
        __syncwarp();
        float z0 = sb2[j0], z1 = sb2[j1];
#pragma unroll 4
        for (int k = 0; k < 64; ++k) {
            float v = syw[k];
            z0 = fmaf(v, sW2[k * 64 + j0], z0);
            z1 = fmaf(v, sW2[k * 64 + j1], z1);
        }
        float s = z0 + z1, ss = z0 * z0 + z1 * z1;
#pragma unroll
        for (int o = 16; o > 0; o >>= 1) {
            s  += __shfl_xor_sync(0xffffffffu, s, o);
            ss += __shfl_xor_sync(0xffffffffu, ss, o);
        }
        float m  = s * (1.f / 64.f);
        float rs = rsqrtf(ss * (1.f / 64.f) - m * m + 1e-5f);
        float* hp = g_h + n * HID;
        hp[j0] += (z0 - m) * rs * sg[j0] + sbe[j0];
        hp[j1] += (z1 - m) * rs * sg[j1] + sbe[j1];
        __syncwarp();
    }
}

// ---------------- local decoder ----------------
__global__ void __launch_bounds__(128) dec_local_kernel(
    const float* __restrict__ W1, const float* __restrict__ b1,
    const float* __restrict__ W2, const float* __restrict__ b2,
    float* __restrict__ out)
{
    __shared__ float sW1[64 * 64];
    __shared__ float sW2[64 * 6];
    __shared__ float sb1[64];
    __shared__ float sb2[8];
    __shared__ float sy[4][64];
    int tid = threadIdx.x;
    for (int i = tid; i < 64 * 64; i += 128) sW1[i] = W1[i];
    for (int i = tid; i < 64 * 6; i += 128) sW2[i] = W2[i];
    if (tid < 64) sb1[tid] = b1[tid];
    if (tid < 6)  sb2[tid] = b2[tid];
    __syncthreads();

    int lane = tid & 31, warp = tid >> 5;
    int j0 = lane, j1 = lane + 32;
    for (int n = blockIdx.x * 4 + warp; n < NNODES; n += gridDim.x * 4) {
        const float4* Hr = reinterpret_cast<const float4*>(g_h + n * HID);
        float a0 = sb1[j0], a1 = sb1[j1];
#pragma unroll 4
        for (int c = 0; c < 16; ++c) {
            float4 v = Hr[c];
            const float* w = sW1 + 4 * c * 64;
            a0 = fmaf(v.x, w[j0], a0);           a1 = fmaf(v.x, w[j1], a1);
            a0 = fmaf(v.y, w[64 + j0], a0);      a1 = fmaf(v.y, w[64 + j1], a1);
            a0 = fmaf(v.z, w[128 + j0], a0);     a1 = fmaf(v.z, w[128 + j1], a1);
            a0 = fmaf(v.w, w[192 + j0], a0);     a1 = fmaf(v.w, w[192 + j1], a1);
        }
        a0 = silu_f(a0); a1 = silu_f(a1);
        sy[warp][j0] = a0; sy[warp][j1] = a1;
        __syncwarp();
        if (lane < 6) {
            float o = sb2[lane];
#pragma unroll 8
            for (int k = 0; k < 64; ++k) o = fmaf(sy[warp][k], sW2[k * 6 + lane], o);
            out[n * 6 + lane] = o;
        }
        __syncwarp();
    }
}

// ---------------- pooling (hierarchical to avoid 50k-deep atomic contention) ----------------
__global__ void __launch_bounds__(256) pool_kernel(const int* __restrict__ batch)
{
    __shared__ float sacc[NGRAPH * HID];  // 256
    __shared__ int   scnt[NGRAPH];
    int tid = threadIdx.x;
    sacc[tid] = 0.f;
    if (tid < NGRAPH) scnt[tid] = 0;
    __syncthreads();
    int j = tid & 63;
    int r = tid >> 6;
    int base = blockIdx.x * 512;
    int end = min(base + 512, NNODES);
    for (int n = base + r; n < end; n += 4) {
        int b = batch[n];
        atomicAdd(&sacc[b * HID + j], g_h[n * HID + j]);
        if (j == 0) atomicAdd(&scnt[b], 1);
    }
    __syncthreads();
    atomicAdd(&g_pooled[tid], sacc[tid]);
    if (tid < NGRAPH) atomicAdd(&g_cnt[tid], scnt[tid]);
}

// ---------------- global decoder ----------------
__global__ void dec_global_kernel(
    const float* __restrict__ W1, const float* __restrict__ b1,
    const float* __restrict__ W2, const float* __restrict__ b2,
    float* __restrict__ out)
{
    __shared__ float sy[NGRAPH][32];
    int g = threadIdx.x >> 5;
    int lane = threadIdx.x & 31;
    float inv = 1.f / fmaxf((float)g_cnt[g], 1.f);
    float a = b1[lane];
#pragma unroll 8
    for (int k = 0; k < 64; ++k)
        a = fmaf(g_pooled[g * HID + k] * inv, W1[k * 32 + lane], a);
    a = silu_f(a);
    sy[g][lane] = a;
    __syncwarp();
    if (lane < 4) {
        float o = b2[lane];
#pragma unroll 8
        for (int k = 0; k < 32; ++k) o = fmaf(sy[g][k], W2[k * 4 + lane], o);
        out[g * 4 + lane] = o;
    }
}

// ---------------- launch ----------------
extern "C" void kernel_launch(void* const* d_in, const int* in_sizes, int n_in,
                              void* d_out, int out_size)
{
    (void)in_sizes; (void)n_in; (void)out_size;
    const float* x      = (const float*)d_in[0];
    const int*   ei     = (const int*)  d_in[1];
    const float* ea     = (const float*)d_in[2];
    const int*   batch  = (const int*)  d_in[3];
    const float* caseP  = (const float*)d_in[4];
    const float* bcP    = (const float*)d_in[5];
    const float* encW1  = (const float*)d_in[6];
    const float* encb1  = (const float*)d_in[7];
    const float* encW2  = (const float*)d_in[8];
    const float* encb2  = (const float*)d_in[9];
    const float* encg   = (const float*)d_in[10];
    const float* encbe  = (const float*)d_in[11];
    const float* eW1    = (const float*)d_in[12];
    const float* eb1    = (const float*)d_in[13];
    const float* eW2    = (const float*)d_in[14];
    const float* eb2    = (const float*)d_in[15];
    const float* eg     = (const float*)d_in[16];
    const float* ebe    = (const float*)d_in[17];
    const float* nW1    = (const float*)d_in[18];
    const float* nb1    = (const float*)d_in[19];
    const float* nW2    = (const float*)d_in[20];
    const float* nb2    = (const float*)d_in[21];
    const float* ng     = (const float*)d_in[22];
    const float* nbe    = (const float*)d_in[23];
    const float* dlW1   = (const float*)d_in[24];
    const float* dlb1   = (const float*)d_in[25];
    const float* dlW2   = (const float*)d_in[26];
    const float* dlb2   = (const float*)d_in[27];
    const float* dgW1   = (const float*)d_in[28];
    const float* dgb1   = (const float*)d_in[29];
    const float* dgW2   = (const float*)d_in[30];
    const float* dgb2   = (const float*)d_in[31];
    float* out = (float*)d_out;

    const int EDGE_SMEM = (133 * 64 + 64 * 64 + 4 * 64) * 4;   // 51456 B
    const int NODE_SMEM = (128 * 64 + 64 * 64 + 4 * 64 + 4 * 64) * 4; // 51200 B
    cudaFuncSetAttribute(edge_kernel, cudaFuncAttributeMaxDynamicSharedMemorySize, EDGE_SMEM);
    cudaFuncSetAttribute(node_kernel, cudaFuncAttributeMaxDynamicSharedMemorySize, NODE_SMEM);

    encoder_kernel<<<200, 128>>>(x, batch, caseP, bcP,
                                 encW1, encb1, encW2, encb2, encg, encbe);

    for (int l = 0; l < NLAYERS; ++l) {
        zero_agg_kernel<<<512, 256>>>();
        edge_kernel<<<444, 128, EDGE_SMEM>>>(
            ei, ea,
            eW1 + l * 133 * 64, eb1 + l * 64,
            eW2 + l * 64 * 64,  eb2 + l * 64,
            eg + l * 64,        ebe + l * 64);
        node_kernel<<<444, 128, NODE_SMEM>>>(
            nW1 + l * 128 * 64, nb1 + l * 64,
            nW2 + l * 64 * 64,  nb2 + l * 64,
            ng + l * 64,        nbe + l * 64);
    }

    zero_pool_kernel<<<1, 256>>>();
    dec_local_kernel<<<200, 128>>>(dlW1, dlb1, dlW2, dlb2, out);
    pool_kernel<<<(NNODES + 511) / 512, 256>>>(batch);
    dec_global_kernel<<<1, 128>>>(dgW1, dgb1, dgW2, dgb2, out + NNODES * 6);
}

// round 2
// speedup vs baseline: 1.5213x; 1.5213x over previous
#include <cuda_runtime.h>

typedef unsigned long long ull;

#define NNODES 50000
#define NEDGES 1600000
#define NGRAPH 4
#define HID    64
#define NLAYERS 5

// ---------------- device scratch ----------------
__device__ float g_h[NNODES * HID];
__device__ float g_agg[NNODES * HID];
__device__ float g_pooled[NGRAPH * HID];
__device__ int   g_cnt[NGRAPH];

// ---------------- helpers ----------------
__device__ __forceinline__ float silu_f(float x) {
    float t;
    asm("tanh.approx.f32 %0, %1;" : "=f"(t) : "f"(x * 0.5f));
    return x * 0.5f * t + x * 0.5f;
}
__device__ __forceinline__ ull fma2(ull a, ull b, ull c) {
    ull d;
    asm("fma.rn.f32x2 %0, %1, %2, %3;" : "=l"(d) : "l"(a), "l"(b), "l"(c));
    return d;
}
__device__ __forceinline__ ull pack2(float lo, float hi) {
    ull r;
    asm("mov.b64 %0, {%1, %2};" : "=l"(r) : "f"(lo), "f"(hi));
    return r;
}
__device__ __forceinline__ ull dup2(float x) {
    ull r;
    asm("mov.b64 %0, {%1, %1};" : "=l"(r) : "f"(x));
    return r;
}
__device__ __forceinline__ void unpack2(ull v, float& lo, float& hi) {
    asm("mov.b64 {%0, %1}, %2;" : "=f"(lo), "=f"(hi) : "l"(v));
}
__device__ __forceinline__ void red_add4(float* p, float a, float b, float c, float d) {
    asm volatile("red.global.add.v4.f32 [%0], {%1, %2, %3, %4};"
                 :: "l"(p), "f"(a), "f"(b), "f"(c), "f"(d) : "memory");
}

// 16 packed FMAs: edge-pairs aA.x aA.y aB.x aB.y vs 4 duplicated weights
#define FMA16(AA, AB, W0, W1, W2, W3, ACC)                               \
    do {                                                                 \
        ACC[0][0]=fma2(AA.x,W0,ACC[0][0]); ACC[0][1]=fma2(AA.x,W1,ACC[0][1]); \
        ACC[0][2]=fma2(AA.x,W2,ACC[0][2]); ACC[0][3]=fma2(AA.x,W3,ACC[0][3]); \
        ACC[1][0]=fma2(AA.y,W0,ACC[1][0]); ACC[1][1]=fma2(AA.y,W1,ACC[1][1]); \
        ACC[1][2]=fma2(AA.y,W2,ACC[1][2]); ACC[1][3]=fma2(AA.y,W3,ACC[1][3]); \
        ACC[2][0]=fma2(AB.x,W0,ACC[2][0]); ACC[2][1]=fma2(AB.x,W1,ACC[2][1]); \
        ACC[2][2]=fma2(AB.x,W2,ACC[2][2]); ACC[2][3]=fma2(AB.x,W3,ACC[2][3]); \
        ACC[3][0]=fma2(AB.y,W0,ACC[3][0]); ACC[3][1]=fma2(AB.y,W1,ACC[3][1]); \
        ACC[3][2]=fma2(AB.y,W2,ACC[3][2]); ACC[3][3]=fma2(AB.y,W3,ACC[3][3]); \
    } while (0)

// ---------------- zero kernels ----------------
__global__ void zero_agg_kernel() {
    int i = blockIdx.x * blockDim.x + threadIdx.x;
    for (; i < NNODES * HID; i += gridDim.x * blockDim.x) g_agg[i] = 0.f;
}
__global__ void zero_pool_kernel() {
    int t = threadIdx.x;
    if (t < NGRAPH * HID) g_pooled[t] = 0.f;
    if (t < NGRAPH) g_cnt[t] = 0;
}

// ---------------- encoder (small, keep simple) ----------------
__global__ void __launch_bounds__(128) encoder_kernel(
    const float* __restrict__ x, const int* __restrict__ batch,
    const float* __restrict__ caseP, const float* __restrict__ bcP,
    const float* __restrict__ W1, const float* __restrict__ b1,
    const float* __restrict__ W2, const float* __restrict__ b2,
    const float* __restrict__ gam, const float* __restrict__ bet)
{
    __shared__ float sW1[16 * 64];
    __shared__ float sW2[64 * 64];
    __shared__ float sb1[64], sb2[64], sg[64], sbe[64];
    __shared__ float sy[4][64];
    int tid = threadIdx.x;
    for (int i = tid; i < 16 * 64; i += 128) sW1[i] = W1[i];
    for (int i = tid; i < 64 * 64; i += 128) sW2[i] = W2[i];
    if (tid < 64) { sb1[tid] = b1[tid]; sb2[tid] = b2[tid]; sg[tid] = gam[tid]; sbe[tid] = bet[tid]; }
    __syncthreads();

    int lane = tid & 31, warp = tid >> 5;
    int j0 = lane, j1 = lane + 32;
    for (int n = blockIdx.x * 4 + warp; n < NNODES; n += gridDim.x * 4) {
        float in[16];
        const float* xr = x + n * 8;
#pragma unroll
        for (int k = 0; k < 8; ++k) in[k] = xr[k];
        int b = batch[n];
#pragma unroll
        for (int k = 0; k < 4; ++k) in[8 + k]  = caseP[b * 4 + k];
#pragma unroll
        for (int k = 0; k < 4; ++k) in[12 + k] = bcP[b * 4 + k];

        float a0 = sb1[j0], a1 = sb1[j1];
#pragma unroll
        for (int k = 0; k < 16; ++k) {
            a0 = fmaf(in[k], sW1[k * 64 + j0], a0);
            a1 = fmaf(in[k], sW1[k * 64 + j1], a1);
        }
        a0 = silu_f(a0); a1 = silu_f(a1);
        sy[warp][j0] = a0; sy[warp][j1] = a1;
        __syncwarp();
        float z0 = sb2[j0], z1 = sb2[j1];
#pragma unroll 4
        for (int k = 0; k < 64; ++k) {
            float v = sy[warp][k];
            z0 = fmaf(v, sW2[k * 64 + j0], z0);
            z1 = fmaf(v, sW2[k * 64 + j1], z1);
        }
        float s = z0 + z1, ss = z0 * z0 + z1 * z1;
#pragma unroll
        for (int o = 16; o > 0; o >>= 1) {
            s  += __shfl_xor_sync(0xffffffffu, s, o);
            ss += __shfl_xor_sync(0xffffffffu, ss, o);
        }
        float m = s * (1.f / 64.f);
        float rs = rsqrtf(ss * (1.f / 64.f) - m * m + 1e-5f);
        g_h[n * HID + j0] = (z0 - m) * rs * sg[j0] + sbe[j0];
        g_h[n * HID + j1] = (z1 - m) * rs * sg[j1] + sbe[j1];
        __syncwarp();
    }
}

// ---------------- edge MLP v2: register-tiled GEMM ----------------
// block = 256 threads, tile = 128 edges x 64 outputs; thread = 8 edges x 4 outputs
__global__ void __launch_bounds__(256, 2) edge2_kernel(
    const int* __restrict__ ei, const float* __restrict__ ea,
    const float* __restrict__ W1, const float* __restrict__ b1,
    const float* __restrict__ W2, const float* __restrict__ b2,
    const float* __restrict__ gam, const float* __restrict__ bet)
{
    extern __shared__ float smem[];
    float* sW1 = smem;            // 133*64 = 8512
    float* sW2 = sW1 + 8512;      // 4096
    float* sg  = sW2 + 4096;      // 64
    float* sbe = sg + 64;         // 64
    float* buf = sbe + 64;        // 8448 floats (union: in / y / z)
    int*   sdst = (int*)(buf + 8448);  // 128

    const int tid = threadIdx.x;
    for (int i = tid; i < 8512; i += 256) sW1[i] = W1[i];
    for (int i = tid; i < 4096; i += 256) sW2[i] = W2[i];
    if (tid < 64) { sg[tid] = gam[tid]; sbe[tid] = bet[tid]; }

    const int e0 = blockIdx.x * 128;
    if (tid < 128) sdst[tid] = ei[NEDGES + e0 + tid];

    const int tn = tid & 15;        // output quad
    const int tm = tid >> 4;        // edge octet
    const int eg_ = tid & 127;      // gather: edge
    const int kq  = (tid >> 7) * 4; // gather: k sub-offset

    ull acc[4][4];
    {
        float4 bv = *(const float4*)(b1 + tn * 4);
#pragma unroll
        for (int ep = 0; ep < 4; ++ep) {
            acc[ep][0] = dup2(bv.x); acc[ep][1] = dup2(bv.y);
            acc[ep][2] = dup2(bv.z); acc[ep][3] = dup2(bv.w);
        }
    }

    // ---- GEMM1 over chunks: k0..63 = h[dst], k64..127 = h[src] ----
#pragma unroll
    for (int ch = 0; ch < 2; ++ch) {
        int node = ei[(ch == 0 ? NEDGES : 0) + e0 + eg_];
        const float4* hp = (const float4*)(g_h + (ull)node * 64);
        __syncthreads();   // protect previous buf contents
#pragma unroll
        for (int r = 0; r < 8; ++r) {
            int k = r * 8 + kq;
            float4 v = hp[2 * r + (kq >> 2)];
            buf[(k + 0) * 128 + eg_] = v.x;
            buf[(k + 1) * 128 + eg_] = v.y;
            buf[(k + 2) * 128 + eg_] = v.z;
            buf[(k + 3) * 128 + eg_] = v.w;
        }
        __syncthreads();
        const float* wbase = sW1 + ch * 64 * 64;
#pragma unroll 2
        for (int k = 0; k < 64; ++k) {
            const ulonglong2* ar = (const ulonglong2*)(buf + k * 128 + tm * 8);
            ulonglong2 aA = ar[0], aB = ar[1];
            float4 wv = *(const float4*)(wbase + k * 64 + tn * 4);
            ull w0 = dup2(wv.x), w1 = dup2(wv.y), w2 = dup2(wv.z), w3 = dup2(wv.w);
            FMA16(aA, aB, w0, w1, w2, w3, acc);
        }
    }
    // ---- GEMM1: k128..132 = edge_attr ----
    __syncthreads();
    if (tid < 128) {
        const float* er = ea + (ull)(e0 + tid) * 5;
#pragma unroll
        for (int j = 0; j < 5; ++j) buf[j * 128 + tid] = er[j];
    }
    __syncthreads();
#pragma unroll
    for (int k = 0; k < 5; ++k) {
        const ulonglong2* ar = (const ulonglong2*)(buf + k * 128 + tm * 8);
        ulonglong2 aA = ar[0], aB = ar[1];
        float4 wv = *(const float4*)(sW1 + (128 + k) * 64 + tn * 4);
        ull w0 = dup2(wv.x), w1 = dup2(wv.y), w2 = dup2(wv.z), w3 = dup2(wv.w);
        FMA16(aA, aB, w0, w1, w2, w3, acc);
    }
    __syncthreads();

    // ---- silu -> stage y k-major (stride 132) ----
#pragma unroll
    for (int ep = 0; ep < 4; ++ep)
#pragma unroll
        for (int j = 0; j < 4; ++j) {
            float x0, x1;
            unpack2(acc[ep][j], x0, x1);
            *(ull*)(buf + (tn * 4 + j) * 132 + tm * 8 + 2 * ep) = pack2(silu_f(x0), silu_f(x1));
        }
    __syncthreads();

    // ---- GEMM2 ----
    ull acc2[4][4];
    {
        float4 bv = *(const float4*)(b2 + tn * 4);
#pragma unroll
        for (int ep = 0; ep < 4; ++ep) {
            acc2[ep][0] = dup2(bv.x); acc2[ep][1] = dup2(bv.y);
            acc2[ep][2] = dup2(bv.z); acc2[ep][3] = dup2(bv.w);
        }
    }
#pragma unroll 2
    for (int k = 0; k < 64; ++k) {
        const ulonglong2* ar = (const ulonglong2*)(buf + k * 132 + tm * 8);
        ulonglong2 aA = ar[0], aB = ar[1];
        float4 wv = *(const float4*)(sW2 + k * 64 + tn * 4);
        ull w0 = dup2(wv.x), w1 = dup2(wv.y), w2 = dup2(wv.z), w3 = dup2(wv.w);
        FMA16(aA, aB, w0, w1, w2, w3, acc2);
    }
    __syncthreads();

    // ---- stage z edge-major (stride 66) ----
#pragma unroll
    for (int ep = 0; ep < 4; ++ep)
#pragma unroll
        for (int j = 0; j < 4; ++j) {
            float x0, x1;
            unpack2(acc2[ep][j], x0, x1);
            int e = tm * 8 + 2 * ep;
            buf[e * 66 + tn * 4 + j]       = x0;
            buf[(e + 1) * 66 + tn * 4 + j] = x1;
        }
    __syncthreads();

    // ---- per-edge LN + scatter-add ----
    if (tid < 128) {
        const float* z = buf + tid * 66;
        float s = 0.f, ss = 0.f;
#pragma unroll 8
        for (int c = 0; c < 64; ++c) { float v = z[c]; s += v; ss += v * v; }
        float m  = s * (1.f / 64.f);
        float rs = rsqrtf(ss * (1.f / 64.f) - m * m + 1e-5f);
        float* ag = g_agg + (ull)sdst[tid] * 64;
#pragma unroll
        for (int q = 0; q < 16; ++q) {
            float o0 = (z[4 * q + 0] - m) * rs * sg[4 * q + 0] + sbe[4 * q + 0];
            float o1 = (z[4 * q + 1] - m) * rs * sg[4 * q + 1] + sbe[4 * q + 1];
            float o2 = (z[4 * q + 2] - m) * rs * sg[4 * q + 2] + sbe[4 * q + 2];
            float o3 = (z[4 * q + 3] - m) * rs * sg[4 * q + 3] + sbe[4 * q + 3];
            red_add4(ag + 4 * q, o0, o1, o2, o3);
        }
    }
}

// ---------------- node MLP v2: register-tiled GEMM + residual ----------------
__global__ void __launch_bounds__(256, 2) node2_kernel(
    const float* __restrict__ W1, const float* __restrict__ b1,
    const float* __restrict__ W2, const float* __restrict__ b2,
    const float* __restrict__ gam, const float* __restrict__ bet)
{
    extern __shared__ float smem[];
    float* sW1 = smem;            // 128*64 = 8192
    float* sW2 = sW1 + 8192;      // 4096
    float* sg  = sW2 + 4096;      // 64
    float* sbe = sg + 64;         // 64
    float* buf = sbe + 64;        // 8448

    const int tid = threadIdx.x;
    for (int i = tid; i < 8192; i += 256) sW1[i] = W1[i];
    for (int i = tid; i < 4096; i += 256) sW2[i] = W2[i];
    if (tid < 64) { sg[tid] = gam[tid]; sbe[tid] = bet[tid]; }

    const int n0 = blockIdx.x * 128;
    const int tn = tid & 15, tm = tid >> 4;
    const int eg_ = tid & 127;
    const int kq  = (tid >> 7) * 4;

    ull acc[4][4];
    {
        float4 bv = *(const float4*)(b1 + tn * 4);
#pragma unroll
        for (int ep = 0; ep < 4; ++ep) {
            acc[ep][0] = dup2(bv.x); acc[ep][1] = dup2(bv.y);
            acc[ep][2] = dup2(bv.z); acc[ep][3] = dup2(bv.w);
        }
    }

    int ng = n0 + eg_;
    if (ng >= NNODES) ng = 0;   // pad (results discarded)

#pragma unroll
    for (int ch = 0; ch < 2; ++ch) {
        const float* srcp = (ch == 0) ? g_h : g_agg;
        const float4* hp = (const float4*)(srcp + (ull)ng * 64);
        __syncthreads();
#pragma unroll
        for (int r = 0; r < 8; ++r) {
            int k = r * 8 + kq;
            float4 v = hp[2 * r + (kq >> 2)];
            buf[(k + 0) * 128 + eg_] = v.x;
            buf[(k + 1) * 128 + eg_] = v.y;
            buf[(k + 2) * 128 + eg_] = v.z;
            buf[(k + 3) * 128 + eg_] = v.w;
        }
        __syncthreads();
        const float* wbase = sW1 + ch * 64 * 64;
#pragma unroll 2
        for (int k = 0; k < 64; ++k) {
            const ulonglong2* ar = (const ulonglong2*)(buf + k * 128 + tm * 8);
            ulonglong2 aA = ar[0], aB = ar[1];
            float4 wv = *(const float4*)(wbase + k * 64 + tn * 4);
            ull w0 = dup2(wv.x), w1 = dup2(wv.y), w2 = dup2(wv.z), w3 = dup2(wv.w);
            FMA16(aA, aB, w0, w1, w2, w3, acc);
        }
    }
    __syncthreads();

    // silu -> y (k-major stride 132)
#pragma unroll
    for (int ep = 0; ep < 4; ++ep)
#pragma unroll
        for (int j = 0; j < 4; ++j) {
            float x0, x1;
            unpack2(acc[ep][j], x0, x1);
            *(ull*)(buf + (tn * 4 + j) * 132 + tm * 8 + 2 * ep) = pack2(silu_f(x0), silu_f(x1));
        }
    __syncthreads();

    ull acc2[4][4];
    {
        float4 bv = *(const float4*)(b2 + tn * 4);
#pragma unroll
        for (int ep = 0; ep < 4; ++ep) {
            acc2[ep][0] = dup2(bv.x); acc2[ep][1] = dup2(bv.y);
            acc2[ep][2] = dup2(bv.z); acc2[ep][3] = dup2(bv.w);
        }
    }
#pragma unroll 2
    for (int k = 0; k < 64; ++k) {
        const ulonglong2* ar = (const ulonglong2*)(buf + k * 132 + tm * 8);
        ulonglong2 aA = ar[0], aB = ar[1];
        float4 wv = *(const float4*)(sW2 + k * 64 + tn * 4);
        ull w0 = dup2(wv.x), w1 = dup2(wv.y), w2 = dup2(wv.z), w3 = dup2(wv.w);
        FMA16(aA, aB, w0, w1, w2, w3, acc2);
    }
    __syncthreads();

    // z node-major (stride 66)
#pragma unroll
    for (int ep = 0; ep < 4; ++ep)
#pragma unroll
        for (int j = 0; j < 4; ++j) {
            float x0, x1;
            unpack2(acc2[ep][j], x0, x1);
            int e = tm * 8 + 2 * ep;
            buf[e * 66 + tn * 4 + j]       = x0;
            buf[(e + 1) * 66 + tn * 4 + j] = x1;
        }
    __syncthreads();

    // per-node LN + residual
    if (tid < 128 && n0 + tid < NNODES) {
        const float* z = buf + tid * 66;
        float s = 0.f, ss = 0.f;
#pragma unroll 8
        for (int c = 0; c < 64; ++c) { float v = z[c]; s += v; ss += v * v; }
        float m  = s * (1.f / 64.f);
        float rs = rsqrtf(ss * (1.f / 64.f) - m * m + 1e-5f);
        float4* hp = (float4*)(g_h + (ull)(n0 + tid) * 64);
#pragma unroll
        for (int q = 0; q < 16; ++q) {
            float4 hv = hp[q];
            hv.x += (z[4 * q + 0] - m) * rs * sg[4 * q + 0] + sbe[4 * q + 0];
            hv.y += (z[4 * q + 1] - m) * rs * sg[4 * q + 1] + sbe[4 * q + 1];
            hv.z += (z[4 * q + 2] - m) * rs * sg[4 * q + 2] + sbe[4 * q + 2];
            hv.w += (z[4 * q + 3] - m) * rs * sg[4 * q + 3] + sbe[4 * q + 3];
            hp[q] = hv;
        }
    }
}

// ---------------- local decoder ----------------
__global__ void __launch_bounds__(128) dec_local_kernel(
    const float* __restrict__ W1, const float* __restrict__ b1,
    const float* __restrict__ W2, const float* __restrict__ b2,
    float* __restrict__ out)
{
    __shared__ float sW1[64 * 64];
    __shared__ float sW2[64 * 6];
    __shared__ float sb1[64];
    __shared__ float sb2[8];
    __shared__ float sy[4][64];
    int tid = threadIdx.x;
    for (int i = tid; i < 64 * 64; i += 128) sW1[i] = W1[i];
    for (int i = tid; i < 64 * 6; i += 128) sW2[i] = W2[i];
    if (tid < 64) sb1[tid] = b1[tid];
    if (tid < 6)  sb2[tid] = b2[tid];
    __syncthreads();

    int lane = tid & 31, warp = tid >> 5;
    int j0 = lane, j1 = lane + 32;
    for (int n = blockIdx.x * 4 + warp; n < NNODES; n += gridDim.x * 4) {
        const float4* Hr = reinterpret_cast<const float4*>(g_h + n * HID);
        float a0 = sb1[j0], a1 = sb1[j1];
#pragma unroll 4
        for (int c = 0; c < 16; ++c) {
            float4 v = Hr[c];
            const float* w = sW1 + 4 * c * 64;
            a0 = fmaf(v.x, w[j0], a0);           a1 = fmaf(v.x, w[j1], a1);
            a0 = fmaf(v.y, w[64 + j0], a0);      a1 = fmaf(v.y, w[64 + j1], a1);
            a0 = fmaf(v.z, w[128 + j0], a0);     a1 = fmaf(v.z, w[128 + j1], a1);
            a0 = fmaf(v.w, w[192 + j0], a0);     a1 = fmaf(v.w, w[192 + j1], a1);
        }
        a0 = silu_f(a0); a1 = silu_f(a1);
        sy[warp][j0] = a0; sy[warp][j1] = a1;
        __syncwarp();
        if (lane < 6) {
            float o = sb2[lane];
#pragma unroll 8
            for (int k = 0; k < 64; ++k) o = fmaf(sy[warp][k], sW2[k * 6 + lane], o);
            out[n * 6 + lane] = o;
        }
        __syncwarp();
    }
}

// ---------------- pooling ----------------
__global__ void __launch_bounds__(256) pool_kernel(const int* __restrict__ batch)
{
    __shared__ float sacc[NGRAPH * HID];
    __shared__ int   scnt[NGRAPH];
    int tid = threadIdx.x;
    sacc[tid] = 0.f;
    if (tid < NGRAPH) scnt[tid] = 0;
    __syncthreads();
    int j = tid & 63;
    int r = tid >> 6;
    int base = blockIdx.x * 512;
    int end = min(base + 512, NNODES);
    for (int n = base + r; n < end; n += 4) {
        int b = batch[n];
        atomicAdd(&sacc[b * HID + j], g_h[n * HID + j]);
        if (j == 0) atomicAdd(&scnt[b], 1);
    }
    __syncthreads();
    atomicAdd(&g_pooled[tid], sacc[tid]);
    if (tid < NGRAPH) atomicAdd(&g_cnt[tid], scnt[tid]);
}

// ---------------- global decoder ----------------
__global__ void dec_global_kernel(
    const float* __restrict__ W1, const float* __restrict__ b1,
    const float* __restrict__ W2, const float* __restrict__ b2,
    float* __restrict__ out)
{
    __shared__ float sy[NGRAPH][32];
    int g = threadIdx.x >> 5;
    int lane = threadIdx.x & 31;
    float inv = 1.f / fmaxf((float)g_cnt[g], 1.f);
    float a = b1[lane];
#pragma unroll 8
    for (int k = 0; k < 64; ++k)
        a = fmaf(g_pooled[g * HID + k] * inv, W1[k * 32 + lane], a);
    a = silu_f(a);
    sy[g][lane] = a;
    __syncwarp();
    if (lane < 4) {
        float o = b2[lane];
#pragma unroll 8
        for (int k = 0; k < 32; ++k) o = fmaf(sy[g][k], W2[k * 4 + lane], o);
        out[g * 4 + lane] = o;
    }
}

// ---------------- launch ----------------
extern "C" void kernel_launch(void* const* d_in, const int* in_sizes, int n_in,
                              void* d_out, int out_size)
{
    (void)in_sizes; (void)n_in; (void)out_size;
    const float* x      = (const float*)d_in[0];
    const int*   ei     = (const int*)  d_in[1];
    const float* ea     = (const float*)d_in[2];
    const int*   batch  = (const int*)  d_in[3];
    const float* caseP  = (const float*)d_in[4];
    const float* bcP    = (const float*)d_in[5];
    const float* encW1  = (const float*)d_in[6];
    const float* encb1  = (const float*)d_in[7];
    const float* encW2  = (const float*)d_in[8];
    const float* encb2  = (const float*)d_in[9];
    const float* encg   = (const float*)d_in[10];
    const float* encbe  = (const float*)d_in[11];
    const float* eW1    = (const float*)d_in[12];
    const float* eb1    = (const float*)d_in[13];
    const float* eW2    = (const float*)d_in[14];
    const float* eb2    = (const float*)d_in[15];
    const float* eg     = (const float*)d_in[16];
    const float* ebe    = (const float*)d_in[17];
    const float* nW1    = (const float*)d_in[18];
    const float* nb1    = (const float*)d_in[19];
    const float* nW2    = (const float*)d_in[20];
    const float* nb2    = (const float*)d_in[21];
    const float* ng     = (const float*)d_in[22];
    const float* nbe    = (const float*)d_in[23];
    const float* dlW1   = (const float*)d_in[24];
    const float* dlb1   = (const float*)d_in[25];
    const float* dlW2   = (const float*)d_in[26];
    const float* dlb2   = (const float*)d_in[27];
    const float* dgW1   = (const float*)d_in[28];
    const float* dgb1   = (const float*)d_in[29];
    const float* dgW2   = (const float*)d_in[30];
    const float* dgb2   = (const float*)d_in[31];
    float* out = (float*)d_out;

    // edge smem: 8512 + 4096 + 128 + 8448 floats + 128 ints
    const int EDGE_SMEM = (8512 + 4096 + 128 + 8448) * 4 + 128 * 4;   // 85248 B
    // node smem: 8192 + 4096 + 128 + 8448 floats
    const int NODE_SMEM = (8192 + 4096 + 128 + 8448) * 4;             // 83456 B
    cudaFuncSetAttribute(edge2_kernel, cudaFuncAttributeMaxDynamicSharedMemorySize, EDGE_SMEM);
    cudaFuncSetAttribute(node2_kernel, cudaFuncAttributeMaxDynamicSharedMemorySize, NODE_SMEM);

    encoder_kernel<<<200, 128>>>(x, batch, caseP, bcP,
                                 encW1, encb1, encW2, encb2, encg, encbe);

    const int EDGE_GRID = NEDGES / 128;             // 12500
    const int NODE_GRID = (NNODES + 127) / 128;     // 391

    for (int l = 0; l < NLAYERS; ++l) {
        zero_agg_kernel<<<256, 256>>>();
        edge2_kernel<<<EDGE_GRID, 256, EDGE_SMEM>>>(
            ei, ea,
            eW1 + l * 133 * 64, eb1 + l * 64,
            eW2 + l * 64 * 64,  eb2 + l * 64,
            eg + l * 64,        ebe + l * 64);
        node2_kernel<<<NODE_GRID, 256, NODE_SMEM>>>(
            nW1 + l * 128 * 64, nb1 + l * 64,
            nW2 + l * 64 * 64,  nb2 + l * 64,
            ng + l * 64,        nbe + l * 64);
    }

    zero_pool_kernel<<<1, 256>>>();
    dec_local_kernel<<<200, 128>>>(dlW1, dlb1, dlW2, dlb2, out);
    pool_kernel<<<(NNODES + 511) / 512, 256>>>(batch);
    dec_global_kernel<<<1, 128>>>(dgW1, dgb1, dgW2, dgb2, out + NNODES * 6);
}

// round 4
// speedup vs baseline: 2.3762x; 1.5620x over previous
#include <cuda_runtime.h>
#include <cuda_bf16.h>

typedef unsigned long long ull;

#define NNODES 50000
#define NEDGES 1600000
#define NGRAPH 4
#define HID    64
#define NLAYERS 5
#define NTILES (NEDGES / 128)   // 12500

// ---------------- device scratch ----------------
__device__ float g_h[NNODES * HID];
__device__ float g_agg[NNODES * HID];
__device__ float g_pooled[NGRAPH * HID];
__device__ int   g_cnt[NGRAPH];
// per-layer prepped bf16 hi/lo weights, [n][k] padded layouts, 61440 B/layer
__device__ __align__(16) unsigned char g_wB[NLAYERS * 61440];

// ---------------- SMEM layout (bytes) ----------------
#define OFF_A    0u        // A hi 128x72 bf16 (18432) + A lo (18432); also zbuf union
#define OFF_AT   36864u    // tail A hi 128x24 bf16 (6144) + lo (6144)
#define OFF_B1   49152u    // B1: H0,L0,H1,L1 each 64x72 bf16 = 9216
#define OFF_B2H  86016u
#define OFF_B2L  95232u
#define OFF_BTH  104448u   // tail B hi 64x24 bf16 = 3072
#define OFF_BTL  107520u
#define OFF_BB1  110592u
#define OFF_BB2  110848u
#define OFF_G    111104u
#define OFF_BE   111360u
#define OFF_SDST 111616u
#define EDGE_SMEM 112128

// ---------------- generic helpers ----------------
__device__ __forceinline__ float silu_f(float x) {
    float t;
    asm("tanh.approx.f32 %0, %1;" : "=f"(t) : "f"(x * 0.5f));
    return x * 0.5f * t + x * 0.5f;
}
__device__ __forceinline__ ull fma2(ull a, ull b, ull c) {
    ull d;
    asm("fma.rn.f32x2 %0, %1, %2, %3;" : "=l"(d) : "l"(a), "l"(b), "l"(c));
    return d;
}
__device__ __forceinline__ ull pack2(float lo, float hi) {
    ull r;
    asm("mov.b64 %0, {%1, %2};" : "=l"(r) : "f"(lo), "f"(hi));
    return r;
}
__device__ __forceinline__ ull dup2(float x) {
    ull r;
    asm("mov.b64 %0, {%1, %1};" : "=l"(r) : "f"(x));
    return r;
}
__device__ __forceinline__ void unpack2(ull v, float& lo, float& hi) {
    asm("mov.b64 {%0, %1}, %2;" : "=f"(lo), "=f"(hi) : "l"(v));
}
__device__ __forceinline__ void red_add4(float* p, float a, float b, float c, float d) {
    asm volatile("red.global.add.v4.f32 [%0], {%1, %2, %3, %4};"
                 :: "l"(p), "f"(a), "f"(b), "f"(c), "f"(d) : "memory");
}
__device__ __forceinline__ unsigned smem_u32(const void* p) {
    unsigned a;
    asm("{ .reg .u64 t; cvta.to.shared.u64 t, %1; cvt.u32.u64 %0, t; }" : "=r"(a) : "l"(p));
    return a;
}

// ---------------- mma.sync helpers ----------------
__device__ __forceinline__ void ldsm4(unsigned* r, unsigned addr) {
    asm volatile("ldmatrix.sync.aligned.m8n8.x4.shared.b16 {%0,%1,%2,%3}, [%4];"
                 : "=r"(r[0]), "=r"(r[1]), "=r"(r[2]), "=r"(r[3]) : "r"(addr));
}
__device__ __forceinline__ void mma16816(float* c, const unsigned* a, unsigned b0, unsigned b1) {
    asm volatile("mma.sync.aligned.m16n8k16.row.col.f32.bf16.bf16.f32 "
                 "{%0,%1,%2,%3}, {%4,%5,%6,%7}, {%8,%9}, {%0,%1,%2,%3};"
                 : "+f"(c[0]), "+f"(c[1]), "+f"(c[2]), "+f"(c[3])
                 : "r"(a[0]), "r"(a[1]), "r"(a[2]), "r"(a[3]), "r"(b0), "r"(b1));
}

// one split-pass over k: A[32 edges x k] * B[k x 64]
template<int NKT>
__device__ __forceinline__ void mma_pass(float (&acc)[2][8][4], unsigned aB, unsigned bB,
                                         unsigned mtStride, unsigned qStride)
{
#pragma unroll
    for (int kt = 0; kt < NKT; ++kt) {
        unsigned a0[4], a1[4];
        ldsm4(a0, aB + kt * 32);
        ldsm4(a1, aB + mtStride + kt * 32);
#pragma unroll
        for (int q = 0; q < 4; ++q) {
            unsigned b[4];
            ldsm4(b, bB + q * qStride + kt * 32);
            mma16816(acc[0][2 * q],     a0, b[0], b[1]);
            mma16816(acc[0][2 * q + 1], a0, b[2], b[3]);
            mma16816(acc[1][2 * q],     a1, b[0], b[1]);
            mma16816(acc[1][2 * q + 1], a1, b[2], b[3]);
        }
    }
}

// ---------------- zero kernels ----------------
__global__ void zero_agg_kernel() {
    int i = blockIdx.x * blockDim.x + threadIdx.x;
    for (; i < NNODES * HID; i += gridDim.x * blockDim.x) g_agg[i] = 0.f;
}
__global__ void zero_pool_kernel() {
    int t = threadIdx.x;
    if (t < NGRAPH * HID) g_pooled[t] = 0.f;
    if (t < NGRAPH) g_cnt[t] = 0;
}

// ---------------- weight prep: fp32 -> split bf16, padded [n][k] ----------------
__global__ void prep_weights(const float* __restrict__ eW1, const float* __restrict__ eW2) {
    int idx = blockIdx.x * blockDim.x + threadIdx.x;
    if (idx >= NLAYERS * 13312) return;
    int l = idx / 13312, r = idx % 13312;
    unsigned char* base = g_wB + l * 61440;
    float w;
    unsigned offH, offL;
    if (r < 8192) {                        // B1 chunks (k rows 0..127 of W1)
        int c = r >> 12, rr = r & 4095, n = rr >> 6, kk = rr & 63;
        w = eW1[l * 133 * 64 + (c * 64 + kk) * 64 + n];
        unsigned o = (unsigned)(n * 144 + kk * 2);
        offH = c * 18432 + o; offL = offH + 9216;
    } else if (r < 12288) {                // B2
        int rr = r - 8192, n = rr >> 6, kk = rr & 63;
        w = eW2[l * 4096 + kk * 64 + n];
        unsigned o = (unsigned)(n * 144 + kk * 2);
        offH = 36864 + o; offL = offH + 9216;
    } else {                               // tail (W1 rows 128..132, zero-padded to 16)
        int rr = r - 12288, n = rr >> 4, j = rr & 15;
        w = (j < 5) ? eW1[l * 133 * 64 + (128 + j) * 64 + n] : 0.f;
        unsigned o = (unsigned)(n * 48 + j * 2);
        offH = 55296 + o; offL = offH + 3072;
    }
    __nv_bfloat16 hi = __float2bfloat16(w);
    __nv_bfloat16 lo = __float2bfloat16(w - __bfloat162float(hi));
    *(__nv_bfloat16*)(base + offH) = hi;
    *(__nv_bfloat16*)(base + offL) = lo;
}

// ---------------- encoder ----------------
__global__ void __launch_bounds__(128) encoder_kernel(
    const float* __restrict__ x, const int* __restrict__ batch,
    const float* __restrict__ caseP, const float* __restrict__ bcP,
    const float* __restrict__ W1, const float* __restrict__ b1,
    const float* __restrict__ W2, const float* __restrict__ b2,
    const float* __restrict__ gam, const float* __restrict__ bet)
{
    __shared__ float sW1[16 * 64];
    __shared__ float sW2[64 * 64];
    __shared__ float sb1[64], sb2[64], sg[64], sbe[64];
    __shared__ float sy[4][64];
    int tid = threadIdx.x;
    for (int i = tid; i < 16 * 64; i += 128) sW1[i] = W1[i];
    for (int i = tid; i < 64 * 64; i += 128) sW2[i] = W2[i];
    if (tid < 64) { sb1[tid] = b1[tid]; sb2[tid] = b2[tid]; sg[tid] = gam[tid]; sbe[tid] = bet[tid]; }
    __syncthreads();

    int lane = tid & 31, warp = tid >> 5;
    int j0 = lane, j1 = lane + 32;
    for (int n = blockIdx.x * 4 + warp; n < NNODES; n += gridDim.x * 4) {
        float in[16];
        const float* xr = x + n * 8;
#pragma unroll
        for (int k = 0; k < 8; ++k) in[k] = xr[k];
        int b = batch[n];
#pragma unroll
        for (int k = 0; k < 4; ++k) in[8 + k]  = caseP[b * 4 + k];
#pragma unroll
        for (int k = 0; k < 4; ++k) in[12 + k] = bcP[b * 4 + k];

        float a0 = sb1[j0], a1 = sb1[j1];
#pragma unroll
        for (int k = 0; k < 16; ++k) {
            a0 = fmaf(in[k], sW1[k * 64 + j0], a0);
            a1 = fmaf(in[k], sW1[k * 64 + j1], a1);
        }
        a0 = silu_f(a0); a1 = silu_f(a1);
        sy[warp][j0] = a0; sy[warp][j1] = a1;
        __syncwarp();
        float z0 = sb2[j0], z1 = sb2[j1];
#pragma unroll 4
        for (int k = 0; k < 64; ++k) {
            float v = sy[warp][k];
            z0 = fmaf(v, sW2[k * 64 + j0], z0);
            z1 = fmaf(v, sW2[k * 64 + j1], z1);
        }
        float s = z0 + z1, ss = z0 * z0 + z1 * z1;
#pragma unroll
        for (int o = 16; o > 0; o >>= 1) {
            s  += __shfl_xor_sync(0xffffffffu, s, o);
            ss += __shfl_xor_sync(0xffffffffu, ss, o);
        }
        float m = s * (1.f / 64.f);
        float rs = rsqrtf(ss * (1.f / 64.f) - m * m + 1e-5f);
        g_h[n * HID + j0] = (z0 - m) * rs * sg[j0] + sbe[j0];
        g_h[n * HID + j1] = (z1 - m) * rs * sg[j1] + sbe[j1];
        __syncwarp();
    }
}

// ---------------- edge MLP v4: mma.sync split-bf16 ----------------
__global__ void __launch_bounds__(128, 2) edge4_kernel(
    const int* __restrict__ ei, const float* __restrict__ ea, int layer,
    const float* __restrict__ b1, const float* __restrict__ b2,
    const float* __restrict__ gam, const float* __restrict__ bet)
{
    extern __shared__ unsigned char sm[];
    const unsigned sbase = smem_u32(sm);
    const int tid = threadIdx.x;
    const int lane = tid & 31, warp = tid >> 5;
    const int gID = lane >> 2, tig = lane & 3;
    const int lt = lane >> 3, lr = lane & 7;

    // --- one-time loads ---
    {
        const uint4* srcw = (const uint4*)(g_wB + layer * 61440);
        uint4* dstw = (uint4*)(sm + OFF_B1);
#pragma unroll 4
        for (int i = tid; i < 3840; i += 128) dstw[i] = srcw[i];
    }
    if (tid < 64) {
        ((float*)(sm + OFF_BB1))[tid] = b1[tid];
        ((float*)(sm + OFF_BB2))[tid] = b2[tid];
        ((float*)(sm + OFF_G))[tid]   = gam[tid];
        ((float*)(sm + OFF_BE))[tid]  = bet[tid];
    }
    for (int i = tid; i < 3072; i += 128) ((unsigned*)(sm + OFF_AT))[i] = 0u;  // zero tail A
    __syncthreads();

    // per-lane ldmatrix offsets
    const unsigned aLane  = (unsigned)((lr + ((lt & 1) << 3)) * 144 + ((lt >> 1) << 4));
    const unsigned bLane  = (unsigned)(((lt >> 1) * 8 + lr) * 144 + ((lt & 1) << 4));
    const unsigned aLaneT = (unsigned)((lr + ((lt & 1) << 3)) * 48  + ((lt >> 1) << 4));
    const unsigned bLaneT = (unsigned)(((lt >> 1) * 8 + lr) * 48  + ((lt & 1) << 4));

    const unsigned AH = sbase + OFF_A;
    const unsigned AL = AH + 18432;
    const unsigned aWarp = (unsigned)(warp * 32 * 144);
    const unsigned ATH = sbase + OFF_AT + (unsigned)(warp * 32 * 48);
    const unsigned ATL = ATH + 6144;
    const float* bb1 = (const float*)(sm + OFF_BB1);
    const float* bb2 = (const float*)(sm + OFF_BB2);
    int* sdst = (int*)(sm + OFF_SDST);

    for (int t = blockIdx.x; t < NTILES; t += gridDim.x) {
        const int e0 = t * 128;
        sdst[tid] = ei[NEDGES + e0 + tid];

        // --- tail A gather (edge_attr -> bf16 hi/lo, cols 0..4, rest stays 0) ---
        {
            const float* ep = ea + (ull)(e0 + tid) * 5;
            float t0 = ep[0], t1 = ep[1], t2 = ep[2], t3 = ep[3], t4 = ep[4];
            unsigned char* th = sm + OFF_AT + tid * 48;
            unsigned char* tl = th + 6144;
            __nv_bfloat162 h01 = __float22bfloat162_rn(make_float2(t0, t1));
            __nv_bfloat162 h23 = __float22bfloat162_rn(make_float2(t2, t3));
            __nv_bfloat162 h45 = __float22bfloat162_rn(make_float2(t4, 0.f));
            float2 f01 = __bfloat1622float2(h01);
            float2 f23 = __bfloat1622float2(h23);
            float2 f45 = __bfloat1622float2(h45);
            __nv_bfloat162 l01 = __float22bfloat162_rn(make_float2(t0 - f01.x, t1 - f01.y));
            __nv_bfloat162 l23 = __float22bfloat162_rn(make_float2(t2 - f23.x, t3 - f23.y));
            __nv_bfloat162 l45 = __float22bfloat162_rn(make_float2(t4 - f45.x, 0.f));
            *(unsigned*)(th + 0) = *(unsigned*)&h01;
            *(unsigned*)(th + 4) = *(unsigned*)&h23;
            *(unsigned*)(th + 8) = *(unsigned*)&h45;
            *(unsigned*)(tl + 0) = *(unsigned*)&l01;
            *(unsigned*)(tl + 4) = *(unsigned*)&l23;
            *(unsigned*)(tl + 8) = *(unsigned*)&l45;
        }

        // --- acc init with b1 ---
        float acc[2][8][4];
#pragma unroll
        for (int nt = 0; nt < 8; ++nt) {
            float2 bv = *(const float2*)(bb1 + nt * 8 + 2 * tig);
#pragma unroll
            for (int mt = 0; mt < 2; ++mt) {
                acc[mt][nt][0] = bv.x; acc[mt][nt][1] = bv.y;
                acc[mt][nt][2] = bv.x; acc[mt][nt][3] = bv.y;
            }
        }

        // --- GEMM1: chunk 0 = h[dst], chunk 1 = h[src] ---
#pragma unroll 1
        for (int c = 0; c < 2; ++c) {
            const int node = ei[(c == 0 ? NEDGES : 0) + e0 + tid];
            const float4* hp = (const float4*)(g_h + (ull)node * 64);
            unsigned char* hrow = sm + OFF_A + tid * 144;
#pragma unroll
            for (int i = 0; i < 16; ++i) {
                float4 v = hp[i];
                __nv_bfloat162 h01 = __float22bfloat162_rn(make_float2(v.x, v.y));
                __nv_bfloat162 h23 = __float22bfloat162_rn(make_float2(v.z, v.w));
                float2 f01 = __bfloat1622float2(h01);
                float2 f23 = __bfloat1622float2(h23);
                __nv_bfloat162 l01 = __float22bfloat162_rn(make_float2(v.x - f01.x, v.y - f01.y));
                __nv_bfloat162 l23 = __float22bfloat162_rn(make_float2(v.z - f23.x, v.w - f23.y));
                *(ull*)(hrow + i * 8)         = ((ull)*(unsigned*)&h23 << 32) | *(unsigned*)&h01;
                *(ull*)(hrow + 18432 + i * 8) = ((ull)*(unsigned*)&l23 << 32) | *(unsigned*)&l01;
            }
            __syncthreads();
            const unsigned bH = sbase + OFF_B1 + (unsigned)c * 18432u + bLane;
            const unsigned bL = bH + 9216u;
#pragma unroll 1
            for (int p = 0; p < 3; ++p) {
                unsigned aB = ((p == 2) ? AL : AH) + aWarp + aLane;
                unsigned bB = (p == 1) ? bL : bH;
                mma_pass<4>(acc, aB, bB, 2304u, 2304u);
            }
            __syncthreads();
        }

        // --- GEMM1 tail: edge_attr chunk (k=16) ---
        {
            const unsigned btH = sbase + OFF_BTH + bLaneT;
            const unsigned btL = sbase + OFF_BTL + bLaneT;
#pragma unroll 1
            for (int p = 0; p < 3; ++p) {
                unsigned aB = ((p == 2) ? ATL : ATH) + aLaneT;
                unsigned bB = (p == 1) ? btL : btH;
                mma_pass<1>(acc, aB, bB, 768u, 768u);
            }
        }

        // --- epilogue1: silu -> split bf16 -> A (y, 128x64) ---
        {
            unsigned char* ybase = sm + OFF_A + (warp * 32 + gID) * 144 + tig * 4;
#pragma unroll
            for (int mt = 0; mt < 2; ++mt)
#pragma unroll
                for (int half = 0; half < 2; ++half) {
                    unsigned char* rowp = ybase + (mt * 16 + half * 8) * 144;
#pragma unroll
                    for (int nt = 0; nt < 8; ++nt) {
                        float y0 = silu_f(acc[mt][nt][2 * half]);
                        float y1 = silu_f(acc[mt][nt][2 * half + 1]);
                        __nv_bfloat162 h = __float22bfloat162_rn(make_float2(y0, y1));
                        float2 f = __bfloat1622float2(h);
                        __nv_bfloat162 l = __float22bfloat162_rn(make_float2(y0 - f.x, y1 - f.y));
                        *(unsigned*)(rowp + nt * 16)         = *(unsigned*)&h;
                        *(unsigned*)(rowp + nt * 16 + 18432) = *(unsigned*)&l;
                    }
                }
        }
        __syncthreads();

        // --- acc re-init with b2, GEMM2 (k=64) ---
#pragma unroll
        for (int nt = 0; nt < 8; ++nt) {
            float2 bv = *(const float2*)(bb2 + nt * 8 + 2 * tig);
#pragma unroll
            for (int mt = 0; mt < 2; ++mt) {
                acc[mt][nt][0] = bv.x; acc[mt][nt][1] = bv.y;
                acc[mt][nt][2] = bv.x; acc[mt][nt][3] = bv.y;
            }
        }
        {
            const unsigned bH = sbase + OFF_B2H + bLane;
            const unsigned bL = sbase + OFF_B2L + bLane;
#pragma unroll 1
            for (int p = 0; p < 3; ++p) {
                unsigned aB = ((p == 2) ? AL : AH) + aWarp + aLane;
                unsigned bB = (p == 1) ? bL : bH;
                mma_pass<4>(acc, aB, bB, 2304u, 2304u);
            }
        }
        __syncthreads();   // all warps done reading A before zbuf overwrite

        // --- stage z (fp32, stride 66) into A region ---
        {
            float* zb = (float*)(sm + OFF_A);
#pragma unroll
            for (int mt = 0; mt < 2; ++mt)
#pragma unroll
                for (int half = 0; half < 2; ++half) {
                    int row = warp * 32 + mt * 16 + half * 8 + gID;
#pragma unroll
                    for (int nt = 0; nt < 8; ++nt) {
                        *(float2*)(zb + row * 66 + nt * 8 + 2 * tig) =
                            make_float2(acc[mt][nt][2 * half], acc[mt][nt][2 * half + 1]);
                    }
                }
        }
        __syncthreads();

        // --- per-edge LayerNorm + scatter-add ---
        {
            const float* z = (const float*)(sm + OFF_A) + tid * 66;
            float s = 0.f, ss = 0.f;
#pragma unroll 8
            for (int c = 0; c < 64; ++c) { float v = z[c]; s += v; ss += v * v; }
            float m  = s * (1.f / 64.f);
            float rs = rsqrtf(ss * (1.f / 64.f) - m * m + 1e-5f);
            const float* sg  = (const float*)(sm + OFF_G);
            const float* sbe = (const float*)(sm + OFF_BE);
            float* ag = g_agg + (ull)sdst[tid] * 64;
#pragma unroll
            for (int q = 0; q < 16; ++q) {
                float o0 = (z[4 * q + 0] - m) * rs * sg[4 * q + 0] + sbe[4 * q + 0];
                float o1 = (z[4 * q + 1] - m) * rs * sg[4 * q + 1] + sbe[4 * q + 1];
                float o2 = (z[4 * q + 2] - m) * rs * sg[4 * q + 2] + sbe[4 * q + 2];
                float o3 = (z[4 * q + 3] - m) * rs * sg[4 * q + 3] + sbe[4 * q + 3];
                red_add4(ag + 4 * q, o0, o1, o2, o3);
            }
        }
        __syncthreads();
    }
}

// ---------------- node MLP (fp32 register-tiled) ----------------
#define FMA16(AA, AB, W0, W1, W2, W3, ACC)                               \
    do {                                                                 \
        ACC[0][0]=fma2(AA.x,W0,ACC[0][0]); ACC[0][1]=fma2(AA.x,W1,ACC[0][1]); \
        ACC[0][2]=fma2(AA.x,W2,ACC[0][2]); ACC[0][3]=fma2(AA.x,W3,ACC[0][3]); \
        ACC[1][0]=fma2(AA.y,W0,ACC[1][0]); ACC[1][1]=fma2(AA.y,W1,ACC[1][1]); \
        ACC[1][2]=fma2(AA.y,W2,ACC[1][2]); ACC[1][3]=fma2(AA.y,W3,ACC[1][3]); \
        ACC[2][0]=fma2(AB.x,W0,ACC[2][0]); ACC[2][1]=fma2(AB.x,W1,ACC[2][1]); \
        ACC[2][2]=fma2(AB.x,W2,ACC[2][2]); ACC[2][3]=fma2(AB.x,W3,ACC[2][3]); \
        ACC[3][0]=fma2(AB.y,W0,ACC[3][0]); ACC[3][1]=fma2(AB.y,W1,ACC[3][1]); \
        ACC[3][2]=fma2(AB.y,W2,ACC[3][2]); ACC[3][3]=fma2(AB.y,W3,ACC[3][3]); \
    } while (0)

__global__ void __launch_bounds__(256, 2) node2_kernel(
    const float* __restrict__ W1, const float* __restrict__ b1,
    const float* __restrict__ W2, const float* __restrict__ b2,
    const float* __restrict__ gam, const float* __restrict__ bet)
{
    extern __shared__ float smem[];
    float* sW1 = smem;
    float* sW2 = sW1 + 8192;
    float* sg  = sW2 + 4096;
    float* sbe = sg + 64;
    float* buf = sbe + 64;

    const int tid = threadIdx.x;
    for (int i = tid; i < 8192; i += 256) sW1[i] = W1[i];
    for (int i = tid; i < 4096; i += 256) sW2[i] = W2[i];
    if (tid < 64) { sg[tid] = gam[tid]; sbe[tid] = bet[tid]; }

    const int n0 = blockIdx.x * 128;
    const int tn = tid & 15, tm = tid >> 4;
    const int eg_ = tid & 127;
    const int kq  = (tid >> 7) * 4;

    ull acc[4][4];
    {
        float4 bv = *(const float4*)(b1 + tn * 4);
#pragma unroll
        for (int ep = 0; ep < 4; ++ep) {
            acc[ep][0] = dup2(bv.x); acc[ep][1] = dup2(bv.y);
            acc[ep][2] = dup2(bv.z); acc[ep][3] = dup2(bv.w);
        }
    }

    int ngi = n0 + eg_;
    if (ngi >= NNODES) ngi = 0;

#pragma unroll
    for (int ch = 0; ch < 2; ++ch) {
        const float* srcp = (ch == 0) ? g_h : g_agg;
        const float4* hp = (const float4*)(srcp + (ull)ngi * 64);
        __syncthreads();
#pragma unroll
        for (int r = 0; r < 8; ++r) {
            int k = r * 8 + kq;
            float4 v = hp[2 * r + (kq >> 2)];
            buf[(k + 0) * 128 + eg_] = v.x;
            buf[(k + 1) * 128 + eg_] = v.y;
            buf[(k + 2) * 128 + eg_] = v.z;
            buf[(k + 3) * 128 + eg_] = v.w;
        }
        __syncthreads();
        const float* wbase = sW1 + ch * 64 * 64;
#pragma unroll 2
        for (int k = 0; k < 64; ++k) {
            const ulonglong2* ar = (const ulonglong2*)(buf + k * 128 + tm * 8);
            ulonglong2 aA = ar[0], aB = ar[1];
            float4 wv = *(const float4*)(wbase + k * 64 + tn * 4);
            ull w0 = dup2(wv.x), w1 = dup2(wv.y), w2 = dup2(wv.z), w3 = dup2(wv.w);
            FMA16(aA, aB, w0, w1, w2, w3, acc);
        }
    }
    __syncthreads();

#pragma unroll
    for (int ep = 0; ep < 4; ++ep)
#pragma unroll
        for (int j = 0; j < 4; ++j) {
            float x0, x1;
            unpack2(acc[ep][j], x0, x1);
            *(ull*)(buf + (tn * 4 + j) * 132 + tm * 8 + 2 * ep) = pack2(silu_f(x0), silu_f(x1));
        }
    __syncthreads();

    ull acc2[4][4];
    {
        float4 bv = *(const float4*)(b2 + tn * 4);
#pragma unroll
        for (int ep = 0; ep < 4; ++ep) {
            acc2[ep][0] = dup2(bv.x); acc2[ep][1] = dup2(bv.y);
            acc2[ep][2] = dup2(bv.z); acc2[ep][3] = dup2(bv.w);
        }
    }
#pragma unroll 2
    for (int k = 0; k < 64; ++k) {
        const ulonglong2* ar = (const ulonglong2*)(buf + k * 132 + tm * 8);
        ulonglong2 aA = ar[0], aB = ar[1];
        float4 wv = *(const float4*)(sW2 + k * 64 + tn * 4);
        ull w0 = dup2(wv.x), w1 = dup2(wv.y), w2 = dup2(wv.z), w3 = dup2(wv.w);
        FMA16(aA, aB, w0, w1, w2, w3, acc2);
    }
    __syncthreads();

#pragma unroll
    for (int ep = 0; ep < 4; ++ep)
#pragma unroll
        for (int j = 0; j < 4; ++j) {
            float x0, x1;
            unpack2(acc2[ep][j], x0, x1);
            int e = tm * 8 + 2 * ep;
            buf[e * 66 + tn * 4 + j]       = x0;
            buf[(e + 1) * 66 + tn * 4 + j] = x1;
        }
    __syncthreads();

    if (tid < 128 && n0 + tid < NNODES) {
        const float* z = buf + tid * 66;
        float s = 0.f, ss = 0.f;
#pragma unroll 8
        for (int c = 0; c < 64; ++c) { float v = z[c]; s += v; ss += v * v; }
        float m  = s * (1.f / 64.f);
        float rs = rsqrtf(ss * (1.f / 64.f) - m * m + 1e-5f);
        float4* hp = (float4*)(g_h + (ull)(n0 + tid) * 64);
#pragma unroll
        for (int q = 0; q < 16; ++q) {
            float4 hv = hp[q];
            hv.x += (z[4 * q + 0] - m) * rs * sg[4 * q + 0] + sbe[4 * q + 0];
            hv.y += (z[4 * q + 1] - m) * rs * sg[4 * q + 1] + sbe[4 * q + 1];
            hv.z += (z[4 * q + 2] - m) * rs * sg[4 * q + 2] + sbe[4 * q + 2];
            hv.w += (z[4 * q + 3] - m) * rs * sg[4 * q + 3] + sbe[4 * q + 3];
            hp[q] = hv;
        }
    }
}

// ---------------- local decoder ----------------
__global__ void __launch_bounds__(128) dec_local_kernel(
    const float* __restrict__ W1, const float* __restrict__ b1,
    const float* __restrict__ W2, const float* __restrict__ b2,
    float* __restrict__ out)
{
    __shared__ float sW1[64 * 64];
    __shared__ float sW2[64 * 6];
    __shared__ float sb1[64];
    __shared__ float sb2[8];
    __shared__ float sy[4][64];
    int tid = threadIdx.x;
    for (int i = tid; i < 64 * 64; i += 128) sW1[i] = W1[i];
    for (int i = tid; i < 64 * 6; i += 128) sW2[i] = W2[i];
    if (tid < 64) sb1[tid] = b1[tid];
    if (tid < 6)  sb2[tid] = b2[tid];
    __syncthreads();

    int lane = tid & 31, warp = tid >> 5;
    int j0 = lane, j1 = lane + 32;
    for (int n = blockIdx.x * 4 + warp; n < NNODES; n += gridDim.x * 4) {
        const float4* Hr = reinterpret_cast<const float4*>(g_h + n * HID);
        float a0 = sb1[j0], a1 = sb1[j1];
#pragma unroll 4
        for (int c = 0; c < 16; ++c) {
            float4 v = Hr[c];
            const float* w = sW1 + 4 * c * 64;
            a0 = fmaf(v.x, w[j0], a0);           a1 = fmaf(v.x, w[j1], a1);
            a0 = fmaf(v.y, w[64 + j0], a0);      a1 = fmaf(v.y, w[64 + j1], a1);
            a0 = fmaf(v.z, w[128 + j0], a0);     a1 = fmaf(v.z, w[128 + j1], a1);
            a0 = fmaf(v.w, w[192 + j0], a0);     a1 = fmaf(v.w, w[192 + j1], a1);
        }
        a0 = silu_f(a0); a1 = silu_f(a1);
        sy[warp][j0] = a0; sy[warp][j1] = a1;
        __syncwarp();
        if (lane < 6) {
            float o = sb2[lane];
#pragma unroll 8
            for (int k = 0; k < 64; ++k) o = fmaf(sy[warp][k], sW2[k * 6 + lane], o);
            out[n * 6 + lane] = o;
        }
        __syncwarp();
    }
}

// ---------------- pooling ----------------
__global__ void __launch_bounds__(256) pool_kernel(const int* __restrict__ batch)
{
    __shared__ float sacc[NGRAPH * HID];
    __shared__ int   scnt[NGRAPH];
    int tid = threadIdx.x;
    sacc[tid] = 0.f;
    if (tid < NGRAPH) scnt[tid] = 0;
    __syncthreads();
    int j = tid & 63;
    int r = tid >> 6;
    int base = blockIdx.x * 512;
    int end = min(base + 512, NNODES);
    for (int n = base + r; n < end; n += 4) {
        int b = batch[n];
        atomicAdd(&sacc[b * HID + j], g_h[n * HID + j]);
        if (j == 0) atomicAdd(&scnt[b], 1);
    }
    __syncthreads();
    atomicAdd(&g_pooled[tid], sacc[tid]);
    if (tid < NGRAPH) atomicAdd(&g_cnt[tid], scnt[tid]);
}

// ---------------- global decoder ----------------
__global__ void dec_global_kernel(
    const float* __restrict__ W1, const float* __restrict__ b1,
    const float* __restrict__ W2, const float* __restrict__ b2,
    float* __restrict__ out)
{
    __shared__ float sy[NGRAPH][32];
    int g = threadIdx.x >> 5;
    int lane = threadIdx.x & 31;
    float inv = 1.f / fmaxf((float)g_cnt[g], 1.f);
    float a = b1[lane];
#pragma unroll 8
    for (int k = 0; k < 64; ++k)
        a = fmaf(g_pooled[g * HID + k] * inv, W1[k * 32 + lane], a);
    a = silu_f(a);
    sy[g][lane] = a;
    __syncwarp();
    if (lane < 4) {
        float o = b2[lane];
#pragma unroll 8
        for (int k = 0; k < 32; ++k) o = fmaf(sy[g][k], W2[k * 4 + lane], o);
        out[g * 4 + lane] = o;
    }
}

// ---------------- launch ----------------
extern "C" void kernel_launch(void* const* d_in, const int* in_sizes, int n_in,
                              void* d_out, int out_size)
{
    (void)in_sizes; (void)n_in; (void)out_size;
    const float* x      = (const float*)d_in[0];
    const int*   ei     = (const int*)  d_in[1];
    const float* ea     = (const float*)d_in[2];
    const int*   batch  = (const int*)  d_in[3];
    const float* caseP  = (const float*)d_in[4];
    const float* bcP    = (const float*)d_in[5];
    const float* encW1  = (const float*)d_in[6];
    const float* encb1  = (const float*)d_in[7];
    const float* encW2  = (const float*)d_in[8];
    const float* encb2  = (const float*)d_in[9];
    const float* encg   = (const float*)d_in[10];
    const float* encbe  = (const float*)d_in[11];
    const float* eW1    = (const float*)d_in[12];
    const float* eb1    = (const float*)d_in[13];
    const float* eW2    = (const float*)d_in[14];
    const float* eb2    = (const float*)d_in[15];
    const float* egm    = (const float*)d_in[16];
    const float* ebe    = (const float*)d_in[17];
    const float* nW1    = (const float*)d_in[18];
    const float* nb1    = (const float*)d_in[19];
    const float* nW2    = (const float*)d_in[20];
    const float* nb2    = (const float*)d_in[21];
    const float* ngm    = (const float*)d_in[22];
    const float* nbe    = (const float*)d_in[23];
    const float* dlW1   = (const float*)d_in[24];
    const float* dlb1   = (const float*)d_in[25];
    const float* dlW2   = (const float*)d_in[26];
    const float* dlb2   = (const float*)d_in[27];
    const float* dgW1   = (const float*)d_in[28];
    const float* dgb1   = (const float*)d_in[29];
    const float* dgW2   = (const float*)d_in[30];
    const float* dgb2   = (const float*)d_in[31];
    float* out = (float*)d_out;

    const int NODE_SMEM = (8192 + 4096 + 128 + 8448) * 4;
    cudaFuncSetAttribute(edge4_kernel, cudaFuncAttributeMaxDynamicSharedMemorySize, EDGE_SMEM);
    cudaFuncSetAttribute(node2_kernel, cudaFuncAttributeMaxDynamicSharedMemorySize, NODE_SMEM);

    prep_weights<<<(NLAYERS * 13312 + 255) / 256, 256>>>(eW1, eW2);
    encoder_kernel<<<200, 128>>>(x, batch, caseP, bcP,
                                 encW1, encb1, encW2, encb2, encg, encbe);

    const int NODE_GRID = (NNODES + 127) / 128;

    for (int l = 0; l < NLAYERS; ++l) {
        zero_agg_kernel<<<512, 256>>>();
        edge4_kernel<<<296, 128, EDGE_SMEM>>>(
            ei, ea, l,
            eb1 + l * 64, eb2 + l * 64,
            egm + l * 64, ebe + l * 64);
        node2_kernel<<<NODE_GRID, 256, NODE_SMEM>>>(
            nW1 + l * 128 * 64, nb1 + l * 64,
            nW2 + l * 64 * 64,  nb2 + l * 64,
            ngm + l * 64,       nbe + l * 64);
    }

    zero_pool_kernel<<<1, 256>>>();
    dec_local_kernel<<<200, 128>>>(dlW1, dlb1, dlW2, dlb2, out);
    pool_kernel<<<(NNODES + 511) / 512, 256>>>(batch);
    dec_global_kernel<<<1, 128>>>(dgW1, dgb1, dgW2, dgb2, out + NNODES * 6);
}

// round 5
// speedup vs baseline: 3.0838x; 1.2978x over previous
#include <cuda_runtime.h>
#include <cuda_bf16.h>

typedef unsigned long long ull;

#define NNODES 50000
#define NEDGES 1600000
#define NGRAPH 4
#define HID    64
#define NLAYERS 5
#define NTILES (NEDGES / 128)   // 12500

// ---------------- device scratch ----------------
__device__ float g_h[NNODES * HID];
__device__ float g_agg[NNODES * HID];
__device__ float g_pooled[NGRAPH * HID];
__device__ int   g_cnt[NGRAPH];
// per-layer prepped bf16 hi/lo weights [n][k] stride-144: B1(4x9216) + B2(2x9216) = 55296 B
__device__ __align__(16) unsigned char g_wB[NLAYERS * 55296];

// ---------------- SMEM layout (bytes) ----------------
#define OFF_A    0u        // A hi 128x72 bf16 (18432) + A lo (18432)
#define OFF_B1   36864u    // c0H, c0L, c1H, c1L each 9216
#define OFF_B2H  73728u
#define OFF_B2L  82944u
#define OFF_T    92160u    // W1 tail rows 128..132 fp32 [5][64] (1280)
#define OFF_BB1  93440u
#define OFF_BB2  93696u
#define OFF_G    93952u
#define OFF_BE   94208u
#define OFF_SDST 94464u    // 128 ints
#define OFF_SEA  94976u    // 128x5 fp32 (2560)
#define EDGE_SMEM 97536

// ---------------- generic helpers ----------------
__device__ __forceinline__ float silu_f(float x) {
    float t;
    asm("tanh.approx.f32 %0, %1;" : "=f"(t) : "f"(x * 0.5f));
    return x * 0.5f * t + x * 0.5f;
}
__device__ __forceinline__ ull fma2(ull a, ull b, ull c) {
    ull d;
    asm("fma.rn.f32x2 %0, %1, %2, %3;" : "=l"(d) : "l"(a), "l"(b), "l"(c));
    return d;
}
__device__ __forceinline__ ull pack2(float lo, float hi) {
    ull r;
    asm("mov.b64 %0, {%1, %2};" : "=l"(r) : "f"(lo), "f"(hi));
    return r;
}
__device__ __forceinline__ ull dup2(float x) {
    ull r;
    asm("mov.b64 %0, {%1, %1};" : "=l"(r) : "f"(x));
    return r;
}
__device__ __forceinline__ void unpack2(ull v, float& lo, float& hi) {
    asm("mov.b64 {%0, %1}, %2;" : "=f"(lo), "=f"(hi) : "l"(v));
}
__device__ __forceinline__ void red_add4(float* p, float a, float b, float c, float d) {
    asm volatile("red.global.add.v4.f32 [%0], {%1, %2, %3, %4};"
                 :: "l"(p), "f"(a), "f"(b), "f"(c), "f"(d) : "memory");
}
__device__ __forceinline__ unsigned smem_u32(const void* p) {
    unsigned a;
    asm("{ .reg .u64 t; cvta.to.shared.u64 t, %1; cvt.u32.u64 %0, t; }" : "=r"(a) : "l"(p));
    return a;
}

// ---------------- mma.sync helpers ----------------
__device__ __forceinline__ void ldsm4(unsigned* r, unsigned addr) {
    asm volatile("ldmatrix.sync.aligned.m8n8.x4.shared.b16 {%0,%1,%2,%3}, [%4];"
                 : "=r"(r[0]), "=r"(r[1]), "=r"(r[2]), "=r"(r[3]) : "r"(addr));
}
__device__ __forceinline__ void mma16816(float* c, const unsigned* a, unsigned b0, unsigned b1) {
    asm volatile("mma.sync.aligned.m16n8k16.row.col.f32.bf16.bf16.f32 "
                 "{%0,%1,%2,%3}, {%4,%5,%6,%7}, {%8,%9}, {%0,%1,%2,%3};"
                 : "+f"(c[0]), "+f"(c[1]), "+f"(c[2]), "+f"(c[3])
                 : "r"(a[0]), "r"(a[1]), "r"(a[2]), "r"(a[3]), "r"(b0), "r"(b1));
}

// ---------------- zero kernels ----------------
__global__ void zero_agg_kernel() {
    int i = blockIdx.x * blockDim.x + threadIdx.x;
    for (; i < NNODES * HID; i += gridDim.x * blockDim.x) g_agg[i] = 0.f;
}
__global__ void zero_pool_kernel() {
    int t = threadIdx.x;
    if (t < NGRAPH * HID) g_pooled[t] = 0.f;
    if (t < NGRAPH) g_cnt[t] = 0;
}

// ---------------- weight prep: fp32 -> split bf16, padded [n][k] ----------------
__global__ void prep_weights(const float* __restrict__ eW1, const float* __restrict__ eW2) {
    int idx = blockIdx.x * blockDim.x + threadIdx.x;
    if (idx >= NLAYERS * 12288) return;
    int l = idx / 12288, r = idx % 12288;
    unsigned char* base = g_wB + l * 55296;
    float w;
    unsigned offH;
    if (r < 8192) {                        // B1 chunks (k rows 0..127 of W1)
        int c = r >> 12, rr = r & 4095, n = rr >> 6, kk = rr & 63;
        w = eW1[l * 133 * 64 + (c * 64 + kk) * 64 + n];
        offH = (unsigned)(c * 18432 + n * 144 + kk * 2);
    } else {                               // B2
        int rr = r - 8192, n = rr >> 6, kk = rr & 63;
        w = eW2[l * 4096 + kk * 64 + n];
        offH = (unsigned)(36864 + n * 144 + kk * 2);
    }
    __nv_bfloat16 hi = __float2bfloat16(w);
    __nv_bfloat16 lo = __float2bfloat16(w - __bfloat162float(hi));
    *(__nv_bfloat16*)(base + offH) = hi;
    *(__nv_bfloat16*)(base + offH + 9216) = lo;
}

// ---------------- encoder ----------------
__global__ void __launch_bounds__(128) encoder_kernel(
    const float* __restrict__ x, const int* __restrict__ batch,
    const float* __restrict__ caseP, const float* __restrict__ bcP,
    const float* __restrict__ W1, const float* __restrict__ b1,
    const float* __restrict__ W2, const float* __restrict__ b2,
    const float* __restrict__ gam, const float* __restrict__ bet)
{
    __shared__ float sW1[16 * 64];
    __shared__ float sW2[64 * 64];
    __shared__ float sb1[64], sb2[64], sg[64], sbe[64];
    __shared__ float sy[4][64];
    int tid = threadIdx.x;
    for (int i = tid; i < 16 * 64; i += 128) sW1[i] = W1[i];
    for (int i = tid; i < 64 * 64; i += 128) sW2[i] = W2[i];
    if (tid < 64) { sb1[tid] = b1[tid]; sb2[tid] = b2[tid]; sg[tid] = gam[tid]; sbe[tid] = bet[tid]; }
    __syncthreads();

    int lane = tid & 31, warp = tid >> 5;
    int j0 = lane, j1 = lane + 32;
    for (int n = blockIdx.x * 4 + warp; n < NNODES; n += gridDim.x * 4) {
        float in[16];
        const float* xr = x + n * 8;
#pragma unroll
        for (int k = 0; k < 8; ++k) in[k] = xr[k];
        int b = batch[n];
#pragma unroll
        for (int k = 0; k < 4; ++k) in[8 + k]  = caseP[b * 4 + k];
#pragma unroll
        for (int k = 0; k < 4; ++k) in[12 + k] = bcP[b * 4 + k];

        float a0 = sb1[j0], a1 = sb1[j1];
#pragma unroll
        for (int k = 0; k < 16; ++k) {
            a0 = fmaf(in[k], sW1[k * 64 + j0], a0);
            a1 = fmaf(in[k], sW1[k * 64 + j1], a1);
        }
        a0 = silu_f(a0); a1 = silu_f(a1);
        sy[warp][j0] = a0; sy[warp][j1] = a1;
        __syncwarp();
        float z0 = sb2[j0], z1 = sb2[j1];
#pragma unroll 4
        for (int k = 0; k < 64; ++k) {
            float v = sy[warp][k];
            z0 = fmaf(v, sW2[k * 64 + j0], z0);
            z1 = fmaf(v, sW2[k * 64 + j1], z1);
        }
        float s = z0 + z1, ss = z0 * z0 + z1 * z1;
#pragma unroll
        for (int o = 16; o > 0; o >>= 1) {
            s  += __shfl_xor_sync(0xffffffffu, s, o);
            ss += __shfl_xor_sync(0xffffffffu, ss, o);
        }
        float m = s * (1.f / 64.f);
        float rs = rsqrtf(ss * (1.f / 64.f) - m * m + 1e-5f);
        g_h[n * HID + j0] = (z0 - m) * rs * sg[j0] + sbe[j0];
        g_h[n * HID + j1] = (z1 - m) * rs * sg[j1] + sbe[j1];
        __syncwarp();
    }
}

// ---------------- edge MLP v5 ----------------
__global__ void __launch_bounds__(128, 2) edge5_kernel(
    const int* __restrict__ ei, const float* __restrict__ ea, int layer,
    const float* __restrict__ W1full, const float* __restrict__ b1,
    const float* __restrict__ b2,
    const float* __restrict__ gam, const float* __restrict__ bet)
{
    extern __shared__ unsigned char sm[];
    const unsigned sbase = smem_u32(sm);
    const int tid = threadIdx.x;
    const int lane = tid & 31, warp = tid >> 5;
    const int gID = lane >> 2, tig = lane & 3;
    const int lt = lane >> 3, lr = lane & 7;

    // --- one-time loads ---
    {
        const uint4* srcw = (const uint4*)(g_wB + layer * 55296);
        uint4* dstw = (uint4*)(sm + OFF_B1);
#pragma unroll 4
        for (int i = tid; i < 3456; i += 128) dstw[i] = srcw[i];
    }
    for (int i = tid; i < 320; i += 128) ((float*)(sm + OFF_T))[i] = W1full[128 * 64 + i];
    if (tid < 64) {
        ((float*)(sm + OFF_BB1))[tid] = b1[tid];
        ((float*)(sm + OFF_BB2))[tid] = b2[tid];
        ((float*)(sm + OFF_G))[tid]   = gam[tid];
        ((float*)(sm + OFF_BE))[tid]  = bet[tid];
    }
    __syncthreads();

    // ldmatrix lane addressing
    const unsigned aLane = (unsigned)((lr + ((lt & 1) << 3)) * 144 + ((lt >> 1) << 4));
    const unsigned bLane = (unsigned)(((lt >> 1) * 8 + lr) * 144 + ((lt & 1) << 4));
    const unsigned AHb = sbase + OFF_A + (unsigned)(warp * 32 * 144) + aLane;
    const unsigned ALb = AHb + 18432u;
    const float* bb1 = (const float*)(sm + OFF_BB1);
    int* sdst = (int*)(sm + OFF_SDST);
    float* sea = (float*)(sm + OFF_SEA);

    for (int t = blockIdx.x; t < NTILES; t += gridDim.x) {
        __syncthreads();   // protect sdst/sea/A against previous tile's readers
        const int e0 = t * 128;
        sdst[tid] = ei[NEDGES + e0 + tid];
        for (int i = tid; i < 640; i += 128) sea[i] = ea[(ull)e0 * 5 + i];

        // acc init with b1 (C-frag layout: cols 8nt+2tig)
        float acc[2][8][4];
#pragma unroll
        for (int nt = 0; nt < 8; ++nt) {
            float2 bv = *(const float2*)(bb1 + nt * 8 + 2 * tig);
#pragma unroll
            for (int mt = 0; mt < 2; ++mt) {
                acc[mt][nt][0] = bv.x; acc[mt][nt][1] = bv.y;
                acc[mt][nt][2] = bv.x; acc[mt][nt][3] = bv.y;
            }
        }

        // ===== GEMM1: chunk0 = h[dst], chunk1 = h[src] =====
#pragma unroll 1
        for (int c = 0; c < 2; ++c) {
            const int node = ei[(c == 0 ? NEDGES : 0) + e0 + tid];
            const float4* hp = (const float4*)(g_h + (ull)node * 64);
            unsigned char* hrow = sm + OFF_A + tid * 144;
#pragma unroll
            for (int i = 0; i < 16; ++i) {
                float4 v = hp[i];
                __nv_bfloat162 h01 = __float22bfloat162_rn(make_float2(v.x, v.y));
                __nv_bfloat162 h23 = __float22bfloat162_rn(make_float2(v.z, v.w));
                float2 f01 = __bfloat1622float2(h01);
                float2 f23 = __bfloat1622float2(h23);
                __nv_bfloat162 l01 = __float22bfloat162_rn(make_float2(v.x - f01.x, v.y - f01.y));
                __nv_bfloat162 l23 = __float22bfloat162_rn(make_float2(v.z - f23.x, v.w - f23.y));
                *(ull*)(hrow + i * 8)         = ((ull)*(unsigned*)&h23 << 32) | *(unsigned*)&h01;
                *(ull*)(hrow + 18432 + i * 8) = ((ull)*(unsigned*)&l23 << 32) | *(unsigned*)&l01;
            }
            __syncthreads();

            const unsigned bH = sbase + OFF_B1 + (unsigned)c * 18432u + bLane;
            const unsigned bL = bH + 9216u;

            // hold BH fragments in registers (reused by pass0 and pass1)
            unsigned BHf[4][4][4];
#pragma unroll
            for (int kt = 0; kt < 4; ++kt)
#pragma unroll
                for (int q = 0; q < 4; ++q)
                    ldsm4(BHf[kt][q], bH + q * 2304u + kt * 32u);

            // pass0: AH x BH
#pragma unroll
            for (int kt = 0; kt < 4; ++kt) {
                unsigned a0[4], a1[4];
                ldsm4(a0, AHb + kt * 32u);
                ldsm4(a1, AHb + 2304u + kt * 32u);
#pragma unroll
                for (int q = 0; q < 4; ++q) {
                    mma16816(acc[0][2 * q],     a0, BHf[kt][q][0], BHf[kt][q][1]);
                    mma16816(acc[0][2 * q + 1], a0, BHf[kt][q][2], BHf[kt][q][3]);
                    mma16816(acc[1][2 * q],     a1, BHf[kt][q][0], BHf[kt][q][1]);
                    mma16816(acc[1][2 * q + 1], a1, BHf[kt][q][2], BHf[kt][q][3]);
                }
            }
            // pass1: AL x BH (BH reused from regs)
#pragma unroll
            for (int kt = 0; kt < 4; ++kt) {
                unsigned a0[4], a1[4];
                ldsm4(a0, ALb + kt * 32u);
                ldsm4(a1, ALb + 2304u + kt * 32u);
#pragma unroll
                for (int q = 0; q < 4; ++q) {
                    mma16816(acc[0][2 * q],     a0, BHf[kt][q][0], BHf[kt][q][1]);
                    mma16816(acc[0][2 * q + 1], a0, BHf[kt][q][2], BHf[kt][q][3]);
                    mma16816(acc[1][2 * q],     a1, BHf[kt][q][0], BHf[kt][q][1]);
                    mma16816(acc[1][2 * q + 1], a1, BHf[kt][q][2], BHf[kt][q][3]);
                }
            }
            // pass2: AH x BL (BL transient)
#pragma unroll
            for (int kt = 0; kt < 4; ++kt) {
                unsigned a0[4], a1[4];
                ldsm4(a0, AHb + kt * 32u);
                ldsm4(a1, AHb + 2304u + kt * 32u);
#pragma unroll
                for (int q = 0; q < 4; ++q) {
                    unsigned bl[4];
                    ldsm4(bl, bL + q * 2304u + kt * 32u);
                    mma16816(acc[0][2 * q],     a0, bl[0], bl[1]);
                    mma16816(acc[0][2 * q + 1], a0, bl[2], bl[3]);
                    mma16816(acc[1][2 * q],     a1, bl[0], bl[1]);
                    mma16816(acc[1][2 * q + 1], a1, bl[2], bl[3]);
                }
            }
            if (c == 0) __syncthreads();   // before chunk1 gather overwrites A
        }

        // ===== epilogue1 (registers): fp32 edge_attr tail + silu + split =====
        float eav[2][2][5];
#pragma unroll
        for (int mt = 0; mt < 2; ++mt)
#pragma unroll
            for (int h = 0; h < 2; ++h) {
                const float* er = sea + (warp * 32 + mt * 16 + h * 8 + gID) * 5;
#pragma unroll
                for (int j = 0; j < 5; ++j) eav[mt][h][j] = er[j];
            }
        unsigned uh[2][2][8], ulo[2][2][8];
#pragma unroll
        for (int nt = 0; nt < 8; ++nt) {
            float2 w[5];
#pragma unroll
            for (int j = 0; j < 5; ++j)
                w[j] = *(const float2*)(sm + OFF_T + (unsigned)((j * 64 + nt * 8 + tig * 2) * 4));
#pragma unroll
            for (int mt = 0; mt < 2; ++mt)
#pragma unroll
                for (int h = 0; h < 2; ++h) {
                    float y0 = acc[mt][nt][2 * h], y1 = acc[mt][nt][2 * h + 1];
#pragma unroll
                    for (int j = 0; j < 5; ++j) {
                        y0 = fmaf(eav[mt][h][j], w[j].x, y0);
                        y1 = fmaf(eav[mt][h][j], w[j].y, y1);
                    }
                    y0 = silu_f(y0); y1 = silu_f(y1);
                    __nv_bfloat162 hb = __float22bfloat162_rn(make_float2(y0, y1));
                    float2 f = __bfloat1622float2(hb);
                    __nv_bfloat162 lb = __float22bfloat162_rn(make_float2(y0 - f.x, y1 - f.y));
                    uh[mt][h][nt]  = *(unsigned*)&hb;
                    ulo[mt][h][nt] = *(unsigned*)&lb;
                }
        }

        // ===== GEMM2 (A from registers, B from SMEM) =====
        float acc2[2][8][4];
#pragma unroll
        for (int nt = 0; nt < 8; ++nt) {
            float2 bv = *(const float2*)(sm + OFF_BB2 + (unsigned)((nt * 8 + tig * 2) * 4));
#pragma unroll
            for (int mt = 0; mt < 2; ++mt) {
                acc2[mt][nt][0] = bv.x; acc2[mt][nt][1] = bv.y;
                acc2[mt][nt][2] = bv.x; acc2[mt][nt][3] = bv.y;
            }
        }
        const unsigned b2H = sbase + OFF_B2H + bLane;
        const unsigned b2L = sbase + OFF_B2L + bLane;
#pragma unroll
        for (int p = 0; p < 3; ++p) {
            const unsigned bB = (p == 1) ? b2L : b2H;
#pragma unroll
            for (int kt = 0; kt < 4; ++kt) {
                unsigned af0[4], af1[4];
                if (p == 2) {
                    af0[0] = ulo[0][0][2 * kt]; af0[1] = ulo[0][1][2 * kt];
                    af0[2] = ulo[0][0][2 * kt + 1]; af0[3] = ulo[0][1][2 * kt + 1];
                    af1[0] = ulo[1][0][2 * kt]; af1[1] = ulo[1][1][2 * kt];
                    af1[2] = ulo[1][0][2 * kt + 1]; af1[3] = ulo[1][1][2 * kt + 1];
                } else {
                    af0[0] = uh[0][0][2 * kt]; af0[1] = uh[0][1][2 * kt];
                    af0[2] = uh[0][0][2 * kt + 1]; af0[3] = uh[0][1][2 * kt + 1];
                    af1[0] = uh[1][0][2 * kt]; af1[1] = uh[1][1][2 * kt];
                    af1[2] = uh[1][0][2 * kt + 1]; af1[3] = uh[1][1][2 * kt + 1];
                }
#pragma unroll
                for (int q = 0; q < 4; ++q) {
                    unsigned b[4];
                    ldsm4(b, bB + q * 2304u + kt * 32u);
                    mma16816(acc2[0][2 * q],     af0, b[0], b[1]);
                    mma16816(acc2[0][2 * q + 1], af0, b[2], b[3]);
                    mma16816(acc2[1][2 * q],     af1, b[0], b[1]);
                    mma16816(acc2[1][2 * q + 1], af1, b[2], b[3]);
                }
            }
        }

        // ===== epilogue2: LayerNorm (shuffles) + scatter (red.v4) =====
        float mArr[2][2], rsArr[2][2];
#pragma unroll
        for (int mt = 0; mt < 2; ++mt)
#pragma unroll
            for (int h = 0; h < 2; ++h) {
                float s = 0.f, ssum = 0.f;
#pragma unroll
                for (int nt = 0; nt < 8; ++nt) {
                    float v0 = acc2[mt][nt][2 * h], v1 = acc2[mt][nt][2 * h + 1];
                    s += v0 + v1; ssum += v0 * v0 + v1 * v1;
                }
                s    += __shfl_xor_sync(0xffffffffu, s, 1);
                ssum += __shfl_xor_sync(0xffffffffu, ssum, 1);
                s    += __shfl_xor_sync(0xffffffffu, s, 2);
                ssum += __shfl_xor_sync(0xffffffffu, ssum, 2);
                float m = s * (1.f / 64.f);
                mArr[mt][h]  = m;
                rsArr[mt][h] = rsqrtf(ssum * (1.f / 64.f) - m * m + 1e-5f);
            }
        const int cq = (tig & 1) * 2 + (tig >> 1);
        float4 gq[4], beq[4];
#pragma unroll
        for (int j = 0; j < 4; ++j) {
            gq[j]  = ((const float4*)(sm + OFF_G))[4 * j + cq];
            beq[j] = ((const float4*)(sm + OFF_BE))[4 * j + cq];
        }
        const unsigned colb = (unsigned)((tig & 1) * 8 + (tig >> 1) * 4);
#pragma unroll
        for (int mt = 0; mt < 2; ++mt)
#pragma unroll
            for (int h = 0; h < 2; ++h) {
                int row = warp * 32 + mt * 16 + h * 8 + gID;
                float* ag = g_agg + (ull)sdst[row] * 64 + colb;
                float m = mArr[mt][h], rs = rsArr[mt][h];
#pragma unroll
                for (int j = 0; j < 4; ++j) {
                    ull p0 = pack2(acc2[mt][2 * j][2 * h],     acc2[mt][2 * j][2 * h + 1]);
                    ull p1 = pack2(acc2[mt][2 * j + 1][2 * h], acc2[mt][2 * j + 1][2 * h + 1]);
                    ull sel = (tig & 1) ? p0 : p1;
                    ull rv = __shfl_xor_sync(0xffffffffu, sel, 1);
                    float q0, q1, q2, q3;
                    if (tig & 1) { unpack2(rv, q0, q1); unpack2(p1, q2, q3); }
                    else         { unpack2(p0, q0, q1); unpack2(rv, q2, q3); }
                    float o0 = (q0 - m) * rs * gq[j].x + beq[j].x;
                    float o1 = (q1 - m) * rs * gq[j].y + beq[j].y;
                    float o2 = (q2 - m) * rs * gq[j].z + beq[j].z;
                    float o3 = (q3 - m) * rs * gq[j].w + beq[j].w;
                    red_add4(ag + 16 * j, o0, o1, o2, o3);
                }
            }
    }
}

// ---------------- node MLP (fp32 register-tiled) ----------------
#define FMA16(AA, AB, W0, W1, W2, W3, ACC)                               \
    do {                                                                 \
        ACC[0][0]=fma2(AA.x,W0,ACC[0][0]); ACC[0][1]=fma2(AA.x,W1,ACC[0][1]); \
        ACC[0][2]=fma2(AA.x,W2,ACC[0][2]); ACC[0][3]=fma2(AA.x,W3,ACC[0][3]); \
        ACC[1][0]=fma2(AA.y,W0,ACC[1][0]); ACC[1][1]=fma2(AA.y,W1,ACC[1][1]); \
        ACC[1][2]=fma2(AA.y,W2,ACC[1][2]); ACC[1][3]=fma2(AA.y,W3,ACC[1][3]); \
        ACC[2][0]=fma2(AB.x,W0,ACC[2][0]); ACC[2][1]=fma2(AB.x,W1,ACC[2][1]); \
        ACC[2][2]=fma2(AB.x,W2,ACC[2][2]); ACC[2][3]=fma2(AB.x,W3,ACC[2][3]); \
        ACC[3][0]=fma2(AB.y,W0,ACC[3][0]); ACC[3][1]=fma2(AB.y,W1,ACC[3][1]); \
        ACC[3][2]=fma2(AB.y,W2,ACC[3][2]); ACC[3][3]=fma2(AB.y,W3,ACC[3][3]); \
    } while (0)

__global__ void __launch_bounds__(256, 2) node2_kernel(
    const float* __restrict__ W1, const float* __restrict__ b1,
    const float* __restrict__ W2, const float* __restrict__ b2,
    const float* __restrict__ gam, const float* __restrict__ bet)
{
    extern __shared__ float smem[];
    float* sW1 = smem;
    float* sW2 = sW1 + 8192;
    float* sg  = sW2 + 4096;
    float* sbe = sg + 64;
    float* buf = sbe + 64;

    const int tid = threadIdx.x;
    for (int i = tid; i < 8192; i += 256) sW1[i] = W1[i];
    for (int i = tid; i < 4096; i += 256) sW2[i] = W2[i];
    if (tid < 64) { sg[tid] = gam[tid]; sbe[tid] = bet[tid]; }

    const int n0 = blockIdx.x * 128;
    const int tn = tid & 15, tm = tid >> 4;
    const int eg_ = tid & 127;
    const int kq  = (tid >> 7) * 4;

    ull acc[4][4];
    {
        float4 bv = *(const float4*)(b1 + tn * 4);
#pragma unroll
        for (int ep = 0; ep < 4; ++ep) {
            acc[ep][0] = dup2(bv.x); acc[ep][1] = dup2(bv.y);
            acc[ep][2] = dup2(bv.z); acc[ep][3] = dup2(bv.w);
        }
    }

    int ngi = n0 + eg_;
    if (ngi >= NNODES) ngi = 0;

#pragma unroll
    for (int ch = 0; ch < 2; ++ch) {
        const float* srcp = (ch == 0) ? g_h : g_agg;
        const float4* hp = (const float4*)(srcp + (ull)ngi * 64);
        __syncthreads();
#pragma unroll
        for (int r = 0; r < 8; ++r) {
            int k = r * 8 + kq;
            float4 v = hp[2 * r + (kq >> 2)];
            buf[(k + 0) * 128 + eg_] = v.x;
            buf[(k + 1) * 128 + eg_] = v.y;
            buf[(k + 2) * 128 + eg_] = v.z;
            buf[(k + 3) * 128 + eg_] = v.w;
        }
        __syncthreads();
        const float* wbase = sW1 + ch * 64 * 64;
#pragma unroll 2
        for (int k = 0; k < 64; ++k) {
            const ulonglong2* ar = (const ulonglong2*)(buf + k * 128 + tm * 8);
            ulonglong2 aA = ar[0], aB = ar[1];
            float4 wv = *(const float4*)(wbase + k * 64 + tn * 4);
            ull w0 = dup2(wv.x), w1 = dup2(wv.y), w2 = dup2(wv.z), w3 = dup2(wv.w);
            FMA16(aA, aB, w0, w1, w2, w3, acc);
        }
    }
    __syncthreads();

#pragma unroll
    for (int ep = 0; ep < 4; ++ep)
#pragma unroll
        for (int j = 0; j < 4; ++j) {
            float x0, x1;
            unpack2(acc[ep][j], x0, x1);
            *(ull*)(buf + (tn * 4 + j) * 132 + tm * 8 + 2 * ep) = pack2(silu_f(x0), silu_f(x1));
        }
    __syncthreads();

    ull acc2[4][4];
    {
        float4 bv = *(const float4*)(b2 + tn * 4);
#pragma unroll
        for (int ep = 0; ep < 4; ++ep) {
            acc2[ep][0] = dup2(bv.x); acc2[ep][1] = dup2(bv.y);
            acc2[ep][2] = dup2(bv.z); acc2[ep][3] = dup2(bv.w);
        }
    }
#pragma unroll 2
    for (int k = 0; k < 64; ++k) {
        const ulonglong2* ar = (const ulonglong2*)(buf + k * 132 + tm * 8);
        ulonglong2 aA = ar[0], aB = ar[1];
        float4 wv = *(const float4*)(sW2 + k * 64 + tn * 4);
        ull w0 = dup2(wv.x), w1 = dup2(wv.y), w2 = dup2(wv.z), w3 = dup2(wv.w);
        FMA16(aA, aB, w0, w1, w2, w3, acc2);
    }
    __syncthreads();

#pragma unroll
    for (int ep = 0; ep < 4; ++ep)
#pragma unroll
        for (int j = 0; j < 4; ++j) {
            float x0, x1;
            unpack2(acc2[ep][j], x0, x1);
            int e = tm * 8 + 2 * ep;
            buf[e * 66 + tn * 4 + j]       = x0;
            buf[(e + 1) * 66 + tn * 4 + j] = x1;
        }
    __syncthreads();

    if (tid < 128 && n0 + tid < NNODES) {
        const float* z = buf + tid * 66;
        float s = 0.f, ss = 0.f;
#pragma unroll 8
        for (int c = 0; c < 64; ++c) { float v = z[c]; s += v; ss += v * v; }
        float m  = s * (1.f / 64.f);
        float rs = rsqrtf(ss * (1.f / 64.f) - m * m + 1e-5f);
        float4* hp = (float4*)(g_h + (ull)(n0 + tid) * 64);
#pragma unroll
        for (int q = 0; q < 16; ++q) {
            float4 hv = hp[q];
            hv.x += (z[4 * q + 0] - m) * rs * sg[4 * q + 0] + sbe[4 * q + 0];
            hv.y += (z[4 * q + 1] - m) * rs * sg[4 * q + 1] + sbe[4 * q + 1];
            hv.z += (z[4 * q + 2] - m) * rs * sg[4 * q + 2] + sbe[4 * q + 2];
            hv.w += (z[4 * q + 3] - m) * rs * sg[4 * q + 3] + sbe[4 * q + 3];
            hp[q] = hv;
        }
    }
}

// ---------------- local decoder ----------------
__global__ void __launch_bounds__(128) dec_local_kernel(
    const float* __restrict__ W1, const float* __restrict__ b1,
    const float* __restrict__ W2, const float* __restrict__ b2,
    float* __restrict__ out)
{
    __shared__ float sW1[64 * 64];
    __shared__ float sW2[64 * 6];
    __shared__ float sb1[64];
    __shared__ float sb2[8];
    __shared__ float sy[4][64];
    int tid = threadIdx.x;
    for (int i = tid; i < 64 * 64; i += 128) sW1[i] = W1[i];
    for (int i = tid; i < 64 * 6; i += 128) sW2[i] = W2[i];
    if (tid < 64) sb1[tid] = b1[tid];
    if (tid < 6)  sb2[tid] = b2[tid];
    __syncthreads();

    int lane = tid & 31, warp = tid >> 5;
    int j0 = lane, j1 = lane + 32;
    for (int n = blockIdx.x * 4 + warp; n < NNODES; n += gridDim.x * 4) {
        const float4* Hr = reinterpret_cast<const float4*>(g_h + n * HID);
        float a0 = sb1[j0], a1 = sb1[j1];
#pragma unroll 4
        for (int c = 0; c < 16; ++c) {
            float4 v = Hr[c];
            const float* w = sW1 + 4 * c * 64;
            a0 = fmaf(v.x, w[j0], a0);           a1 = fmaf(v.x, w[j1], a1);
            a0 = fmaf(v.y, w[64 + j0], a0);      a1 = fmaf(v.y, w[64 + j1], a1);
            a0 = fmaf(v.z, w[128 + j0], a0);     a1 = fmaf(v.z, w[128 + j1], a1);
            a0 = fmaf(v.w, w[192 + j0], a0);     a1 = fmaf(v.w, w[192 + j1], a1);
        }
        a0 = silu_f(a0); a1 = silu_f(a1);
        sy[warp][j0] = a0; sy[warp][j1] = a1;
        __syncwarp();
        if (lane < 6) {
            float o = sb2[lane];
#pragma unroll 8
            for (int k = 0; k < 64; ++k) o = fmaf(sy[warp][k], sW2[k * 6 + lane], o);
            out[n * 6 + lane] = o;
        }
        __syncwarp();
    }
}

// ---------------- pooling ----------------
__global__ void __launch_bounds__(256) pool_kernel(const int* __restrict__ batch)
{
    __shared__ float sacc[NGRAPH * HID];
    __shared__ int   scnt[NGRAPH];
    int tid = threadIdx.x;
    sacc[tid] = 0.f;
    if (tid < NGRAPH) scnt[tid] = 0;
    __syncthreads();
    int j = tid & 63;
    int r = tid >> 6;
    int base = blockIdx.x * 512;
    int end = min(base + 512, NNODES);
    for (int n = base + r; n < end; n += 4) {
        int b = batch[n];
        atomicAdd(&sacc[b * HID + j], g_h[n * HID + j]);
        if (j == 0) atomicAdd(&scnt[b], 1);
    }
    __syncthreads();
    atomicAdd(&g_pooled[tid], sacc[tid]);
    if (tid < NGRAPH) atomicAdd(&g_cnt[tid], scnt[tid]);
}

// ---------------- global decoder ----------------
__global__ void dec_global_kernel(
    const float* __restrict__ W1, const float* __restrict__ b1,
    const float* __restrict__ W2, const float* __restrict__ b2,
    float* __restrict__ out)
{
    __shared__ float sy[NGRAPH][32];
    int g = threadIdx.x >> 5;
    int lane = threadIdx.x & 31;
    float inv = 1.f / fmaxf((float)g_cnt[g], 1.f);
    float a = b1[lane];
#pragma unroll 8
    for (int k = 0; k < 64; ++k)
        a = fmaf(g_pooled[g * HID + k] * inv, W1[k * 32 + lane], a);
    a = silu_f(a);
    sy[g][lane] = a;
    __syncwarp();
    if (lane < 4) {
        float o = b2[lane];
#pragma unroll 8
        for (int k = 0; k < 32; ++k) o = fmaf(sy[g][k], W2[k * 4 + lane], o);
        out[g * 4 + lane] = o;
    }
}

// ---------------- launch ----------------
extern "C" void kernel_launch(void* const* d_in, const int* in_sizes, int n_in,
                              void* d_out, int out_size)
{
    (void)in_sizes; (void)n_in; (void)out_size;
    const float* x      = (const float*)d_in[0];
    const int*   ei     = (const int*)  d_in[1];
    const float* ea     = (const float*)d_in[2];
    const int*   batch  = (const int*)  d_in[3];
    const float* caseP  = (const float*)d_in[4];
    const float* bcP    = (const float*)d_in[5];
    const float* encW1  = (const float*)d_in[6];
    const float* encb1  = (const float*)d_in[7];
    const float* encW2  = (const float*)d_in[8];
    const float* encb2  = (const float*)d_in[9];
    const float* encg   = (const float*)d_in[10];
    const float* encbe  = (const float*)d_in[11];
    const float* eW1    = (const float*)d_in[12];
    const float* eb1    = (const float*)d_in[13];
    const float* eW2    = (const float*)d_in[14];
    const float* eb2    = (const float*)d_in[15];
    const float* egm    = (const float*)d_in[16];
    const float* ebe    = (const float*)d_in[17];
    const float* nW1    = (const float*)d_in[18];
    const float* nb1    = (const float*)d_in[19];
    const float* nW2    = (const float*)d_in[20];
    const float* nb2    = (const float*)d_in[21];
    const float* ngm    = (const float*)d_in[22];
    const float* nbe    = (const float*)d_in[23];
    const float* dlW1   = (const float*)d_in[24];
    const float* dlb1   = (const float*)d_in[25];
    const float* dlW2   = (const float*)d_in[26];
    const float* dlb2   = (const float*)d_in[27];
    const float* dgW1   = (const float*)d_in[28];
    const float* dgb1   = (const float*)d_in[29];
    const float* dgW2   = (const float*)d_in[30];
    const float* dgb2   = (const float*)d_in[31];
    float* out = (float*)d_out;

    const int NODE_SMEM = (8192 + 4096 + 128 + 8448) * 4;
    cudaFuncSetAttribute(edge5_kernel, cudaFuncAttributeMaxDynamicSharedMemorySize, EDGE_SMEM);
    cudaFuncSetAttribute(node2_kernel, cudaFuncAttributeMaxDynamicSharedMemorySize, NODE_SMEM);

    prep_weights<<<(NLAYERS * 12288 + 255) / 256, 256>>>(eW1, eW2);
    encoder_kernel<<<200, 128>>>(x, batch, caseP, bcP,
                                 encW1, encb1, encW2, encb2, encg, encbe);

    const int NODE_GRID = (NNODES + 127) / 128;

    for (int l = 0; l < NLAYERS; ++l) {
        zero_agg_kernel<<<512, 256>>>();
        edge5_kernel<<<296, 128, EDGE_SMEM>>>(
            ei, ea, l,
            eW1 + l * 133 * 64, eb1 + l * 64, eb2 + l * 64,
            egm + l * 64, ebe + l * 64);
        node2_kernel<<<NODE_GRID, 256, NODE_SMEM>>>(
            nW1 + l * 128 * 64, nb1 + l * 64,
            nW2 + l * 64 * 64,  nb2 + l * 64,
            ngm + l * 64,       nbe + l * 64);
    }

    zero_pool_kernel<<<1, 256>>>();
    dec_local_kernel<<<200, 128>>>(dlW1, dlb1, dlW2, dlb2, out);
    pool_kernel<<<(NNODES + 511) / 512, 256>>>(batch);
    dec_global_kernel<<<1, 128>>>(dgW1, dgb1, dgW2, dgb2, out + NNODES * 6);
}